// round 10
// baseline (speedup 1.0000x reference)
#include <cuda_runtime.h>
#include <math.h>

#define TT   30
#define BB   32
#define VV   32
#define FF   128
#define LL   256
#define LFF  64
#define HH   8
#define DHH  16
#define HISTN 10
#define MROWS (TT*BB*VV)   // 30720

typedef unsigned long long u64;

// ---- packed f32x2 helpers (sm_100+ PTX; per-lane IEEE fp32 FMA) ----
__device__ __forceinline__ u64 pk2(float a, float b) {
    u64 r; asm("mov.b64 %0,{%1,%2};" : "=l"(r) : "f"(a), "f"(b)); return r;
}
__device__ __forceinline__ float2 up2(u64 v) {
    float2 f; asm("mov.b64 {%0,%1},%2;" : "=f"(f.x), "=f"(f.y) : "l"(v)); return f;
}
__device__ __forceinline__ void fma2(u64& d, u64 a, u64 b) {
    asm("fma.rn.f32x2 %0,%1,%2,%0;" : "+l"(d) : "l"(a), "l"(b));
}

// ---------------- scratch (no allocations allowed) ----------------
__device__ float g_Kproj[BB*LL*FF];
__device__ float g_LV[BB*LL*FF];
__device__ unsigned char g_mask[BB*LL];
__device__ float g_q[MROWS*FF];
__device__ float g_r[MROWS*FF];
__device__ float g_pre[MROWS*FF];

// ---------------- lane projection ----------------
template<bool LOGSIG>
__global__ __launch_bounds__(256) void lane_proj_kernel(
    const float* __restrict__ lanes, const float* __restrict__ W,
    const float* __restrict__ bias, float* __restrict__ out)
{
    __shared__ float Wsh[LFF][FF + 1];
    __shared__ float lsh[32][LFF];
    __shared__ float bsh[FF];
    int tid = threadIdx.x;
    int row0 = blockIdx.x * 32;

    #pragma unroll
    for (int i = 0; i < 32; i++) {
        int idx = tid + i * 256;
        int f = idx >> 6, j = idx & 63;
        Wsh[j][f] = W[idx];
    }
    if (tid < FF) bsh[tid] = bias[tid];
    #pragma unroll
    for (int i = 0; i < 2; i++) {
        int idx = tid + i * 256;
        int r = idx >> 4;
        int c = (idx & 15) * 4;
        *(float4*)&lsh[r][c] = *(const float4*)(lanes + (size_t)(row0 + r) * LFF + c);
    }
    __syncthreads();

    int f = tid & 127;
    for (int r = tid >> 7; r < 32; r += 2) {
        float acc = bsh[f];
        #pragma unroll
        for (int j = 0; j < LFF; j++) acc += lsh[r][j] * Wsh[j][f];
        if (LOGSIG) {
            acc = (acc >= 0.f) ? -__logf(1.f + __expf(-acc))
                               : acc - __logf(1.f + __expf(acc));
        }
        out[(size_t)(row0 + r) * FF + f] = acc;
    }
}

// ---------------- mask: any over HIST, dtype self-detection ----------------
__global__ void mask_kernel(const unsigned char* __restrict__ m)
{
    int tid = threadIdx.x;
    const unsigned int* w = (const unsigned int*)m;
    bool okI = true, okF = true;
    for (int j = tid; j < (HISTN * BB * LL) / 4; j += 256) {
        unsigned int x = w[j];
        if (x > 1u) okI = false;
        if (x != 0u && x != 0x3F800000u) okF = false;
    }
    okI = __syncthreads_and((int)okI) != 0;
    okF = __syncthreads_and((int)okF) != 0;
    int cls = okI ? 0 : (okF ? 1 : 2);

    for (int i = tid; i < BB * LL; i += 256) {
        unsigned int any = 0;
        #pragma unroll
        for (int h = 0; h < HISTN; h++) {
            int j = h * BB * LL + i;
            unsigned int v;
            if (cls == 0)      v = w[j];
            else if (cls == 1) v = (w[j] != 0u);
            else               v = m[j];
            any |= v;
        }
        g_mask[i] = any ? 1 : 0;
    }
}

// ---------------- 30720x128x128 GEMM (packed f32x2) ----------------
template<bool SUM_AB, bool EPI>
__global__ __launch_bounds__(256) void gemm128_kernel(
    const float* __restrict__ A1, const float* __restrict__ A2,
    const float* __restrict__ W,  const float* __restrict__ bias,
    float* __restrict__ C,
    const float* __restrict__ E1, const float* __restrict__ E2)
{
    __shared__ float Ash[64][36];
    __shared__ float Wsh[32][132];
    int tid = threadIdx.x;
    int tx = tid & 31, ty = tid >> 5;
    int m0 = blockIdx.x * 64;

    u64 acc2[8][2];
    #pragma unroll
    for (int i = 0; i < 8; i++) { acc2[i][0] = 0ull; acc2[i][1] = 0ull; }

    for (int k0 = 0; k0 < 128; k0 += 32) {
        #pragma unroll
        for (int i = 0; i < 2; i++) {
            int idx = tid + i * 256;
            int row = idx >> 3, c = (idx & 7) * 4;
            float4 a = *(const float4*)(A1 + (size_t)(m0 + row) * FF + k0 + c);
            if (SUM_AB) {
                float4 b = *(const float4*)(A2 + (size_t)(m0 + row) * FF + k0 + c);
                a.x += b.x; a.y += b.y; a.z += b.z; a.w += b.w;
            }
            *(float4*)&Ash[row][c] = a;
        }
        #pragma unroll
        for (int i = 0; i < 16; i++) {
            int idx = tid + i * 256;
            int n = idx >> 5, kk = idx & 31;
            Wsh[kk][n] = W[n * FF + k0 + kk];
        }
        __syncthreads();
        #pragma unroll
        for (int k = 0; k < 32; k++) {
            ulonglong2 b2 = *(ulonglong2*)&Wsh[k][tx * 4];
            #pragma unroll
            for (int i = 0; i < 8; i++) {
                float a = Ash[ty * 8 + i][k];
                u64 a2 = pk2(a, a);
                fma2(acc2[i][0], a2, b2.x);
                fma2(acc2[i][1], a2, b2.y);
            }
        }
        __syncthreads();
    }

    int n = tx * 4;
    float4 bb = *(const float4*)(bias + n);
    #pragma unroll
    for (int i = 0; i < 8; i++) {
        int m = m0 + ty * 8 + i;
        float2 lo = up2(acc2[i][0]), hi = up2(acc2[i][1]);
        float4 o;
        o.x = lo.x + bb.x; o.y = lo.y + bb.y;
        o.z = hi.x + bb.z; o.w = hi.y + bb.w;
        if (EPI) {
            float4 e1 = *(const float4*)(E1 + (size_t)m * FF + n);
            float4 e2 = *(const float4*)(E2 + (size_t)m * FF + n);
            o.x += e1.x - e2.x; o.y += e1.y - e2.y;
            o.z += e1.z - e2.z; o.w += e1.w - e2.w;
        }
        *(float4*)(C + (size_t)m * FF + n) = o;
    }
}

// ---------------- fused q+r GEMM (packed f32x2) ----------------
__global__ __launch_bounds__(256, 2) void gemm_qr_kernel(
    const float* __restrict__ A1, const float* __restrict__ A2,
    const float* __restrict__ Wq, const float* __restrict__ bq,
    const float* __restrict__ Wr, const float* __restrict__ br,
    float* __restrict__ Cq, float* __restrict__ Cr)
{
    __shared__ float Ash[64][36];
    __shared__ float W1[32][132];
    __shared__ float W2[32][132];
    int tid = threadIdx.x;
    int tx = tid & 31, ty = tid >> 5;
    int m0 = blockIdx.x * 64;

    u64 aq[8][2], ar[8][2];
    #pragma unroll
    for (int i = 0; i < 8; i++) {
        aq[i][0] = aq[i][1] = 0ull;
        ar[i][0] = ar[i][1] = 0ull;
    }

    for (int k0 = 0; k0 < 128; k0 += 32) {
        #pragma unroll
        for (int i = 0; i < 2; i++) {
            int idx = tid + i * 256;
            int row = idx >> 3, c = (idx & 7) * 4;
            float4 a = *(const float4*)(A1 + (size_t)(m0 + row) * FF + k0 + c);
            float4 b = *(const float4*)(A2 + (size_t)(m0 + row) * FF + k0 + c);
            a.x += b.x; a.y += b.y; a.z += b.z; a.w += b.w;
            *(float4*)&Ash[row][c] = a;
        }
        #pragma unroll
        for (int i = 0; i < 16; i++) {
            int idx = tid + i * 256;
            int n = idx >> 5, kk = idx & 31;
            W1[kk][n] = Wq[n * FF + k0 + kk];
            W2[kk][n] = Wr[n * FF + k0 + kk];
        }
        __syncthreads();
        #pragma unroll
        for (int k = 0; k < 32; k++) {
            ulonglong2 q2 = *(ulonglong2*)&W1[k][tx * 4];
            ulonglong2 r2 = *(ulonglong2*)&W2[k][tx * 4];
            #pragma unroll
            for (int i = 0; i < 8; i++) {
                float a = Ash[ty * 8 + i][k];
                u64 a2 = pk2(a, a);
                fma2(aq[i][0], a2, q2.x);
                fma2(aq[i][1], a2, q2.y);
                fma2(ar[i][0], a2, r2.x);
                fma2(ar[i][1], a2, r2.y);
            }
        }
        __syncthreads();
    }

    int n = tx * 4;
    float4 bq4 = *(const float4*)(bq + n);
    float4 br4 = *(const float4*)(br + n);
    #pragma unroll
    for (int i = 0; i < 8; i++) {
        int m = m0 + ty * 8 + i;
        float2 qlo = up2(aq[i][0]), qhi = up2(aq[i][1]);
        float2 rlo = up2(ar[i][0]), rhi = up2(ar[i][1]);
        float4 oq, orr;
        oq.x  = qlo.x + bq4.x; oq.y  = qlo.y + bq4.y;
        oq.z  = qhi.x + bq4.z; oq.w  = qhi.y + bq4.w;
        orr.x = rlo.x + br4.x; orr.y = rlo.y + br4.y;
        orr.z = rhi.x + br4.z; orr.w = rhi.y + br4.w;
        *(float4*)(Cq + (size_t)m * FF + n) = oq;
        *(float4*)(Cr + (size_t)m * FF + n) = orr;
    }
}

// ---------------- attention v5: small-smem (38.3KB) for occupancy ----------------
// v processed in 2 chunks of 16. Phase B: thread=(vB,qt,dq), l = 4j+qt (interleaved
// so sc scalar reads and lvsh LDS.128 are bank-conflict-free per quarter-warp).
#define TPB5 10
__global__ __launch_bounds__(256, 3) void attn5_kernel()
{
    __shared__ float sc[16][260];       // 16.6 KB: one v-chunk of scores/p
    __shared__ float lvsh[256][16];     // 16 KB
    __shared__ float qsh[32][16];       // 2 KB
    __shared__ float sinv[16];
    __shared__ float pb[256][4];        // 4 KB: phase-B partials

    int tid = threadIdx.x;
    int b = blockIdx.x >> 3, h = blockIdx.x & 7;
    int t0 = blockIdx.y * TPB5;
    int l = tid;
    int warp = tid >> 5, lane = tid & 31;

    // K row for this l in registers
    float4 k0, k1, k2, k3;
    {
        const float* kp = g_Kproj + ((size_t)(b * LL + l)) * FF + h * DHH;
        k0 = *(const float4*)(kp);
        k1 = *(const float4*)(kp + 4);
        k2 = *(const float4*)(kp + 8);
        k3 = *(const float4*)(kp + 12);
        const float* lvp = g_LV + ((size_t)(b * LL + l)) * FF + h * DHH;
        #pragma unroll
        for (int i = 0; i < 4; i++)
            *(float4*)&lvsh[l][i * 4] = *(const float4*)(lvp + i * 4);
    }
    bool mon = g_mask[b * LL + l] != 0;

    // phase-B thread mapping: tid = vB*16 + qt*4 + dq
    int dq = tid & 3;
    int qt = (tid >> 2) & 3;
    int vB = tid >> 4;          // 0..15

    for (int t = t0; t < t0 + TPB5; t++) {
        __syncthreads();                 // qsh reuse
        if (tid < 128) {
            int v = tid >> 2, q4 = tid & 3;
            *(float4*)&qsh[v][q4 * 4] =
                *(const float4*)(g_q + ((size_t)((t * BB + b) * VV + v)) * FF + h * DHH + q4 * 4);
        }
        __syncthreads();

        #pragma unroll
        for (int c = 0; c < 2; c++) {
            // ---- Phase A: scores for 16 v, thread l = column l ----
            #pragma unroll
            for (int v = 0; v < 16; v++) {
                int vg = c * 16 + v;
                float4 q0 = *(float4*)&qsh[vg][0];
                float4 q1 = *(float4*)&qsh[vg][4];
                float4 q2 = *(float4*)&qsh[vg][8];
                float4 q3 = *(float4*)&qsh[vg][12];
                float s = q0.x * k0.x + q0.y * k0.y + q0.z * k0.z + q0.w * k0.w
                        + q1.x * k1.x + q1.y * k1.y + q1.z * k1.z + q1.w * k1.w
                        + q2.x * k2.x + q2.y * k2.y + q2.z * k2.z + q2.w * k2.w
                        + q3.x * k3.x + q3.y * k3.y + q3.z * k3.z + q3.w * k3.w;
                sc[v][l] = mon ? (s * 0.25f) : -1e9f;
            }
            __syncthreads();

            // ---- softmax: 2 rows per warp (rows warp, warp+8) ----
            #pragma unroll
            for (int rr = 0; rr < 2; rr++) {
                int rv = warp + rr * 8;
                float4 a = *(float4*)&sc[rv][lane * 8];
                float4 cc = *(float4*)&sc[rv][lane * 8 + 4];
                float mx = fmaxf(fmaxf(fmaxf(a.x, a.y), fmaxf(a.z, a.w)),
                                 fmaxf(fmaxf(cc.x, cc.y), fmaxf(cc.z, cc.w)));
                #pragma unroll
                for (int o = 16; o > 0; o >>= 1)
                    mx = fmaxf(mx, __shfl_xor_sync(0xffffffffu, mx, o));
                a.x = __expf(a.x - mx); a.y = __expf(a.y - mx);
                a.z = __expf(a.z - mx); a.w = __expf(a.w - mx);
                cc.x = __expf(cc.x - mx); cc.y = __expf(cc.y - mx);
                cc.z = __expf(cc.z - mx); cc.w = __expf(cc.w - mx);
                float sm = a.x + a.y + a.z + a.w + cc.x + cc.y + cc.z + cc.w;
                #pragma unroll
                for (int o = 16; o > 0; o >>= 1)
                    sm += __shfl_xor_sync(0xffffffffu, sm, o);
                *(float4*)&sc[rv][lane * 8] = a;
                *(float4*)&sc[rv][lane * 8 + 4] = cc;
                if (lane == 0) sinv[rv] = __fdividef(1.f, sm);
            }
            __syncthreads();

            // ---- Phase B: partial sums over l = 4j+qt ----
            {
                float4 acc = make_float4(0.f, 0.f, 0.f, 0.f);
                #pragma unroll 8
                for (int j = 0; j < 64; j++) {
                    int ll2 = 4 * j + qt;
                    float p = sc[vB][ll2];
                    float4 lv = *(float4*)&lvsh[ll2][dq * 4];
                    acc.x += p * lv.x; acc.y += p * lv.y;
                    acc.z += p * lv.z; acc.w += p * lv.w;
                }
                *(float4*)&pb[tid][0] = acc;
                __syncthreads();
                if (qt == 0) {
                    float4 o1 = *(float4*)&pb[tid + 4][0];
                    float4 o2 = *(float4*)&pb[tid + 8][0];
                    float4 o3 = *(float4*)&pb[tid + 12][0];
                    acc.x += o1.x + o2.x + o3.x;
                    acc.y += o1.y + o2.y + o3.y;
                    acc.z += o1.z + o2.z + o3.z;
                    acc.w += o1.w + o2.w + o3.w;
                    float si = sinv[vB];
                    int vg = c * 16 + vB;
                    float4 r4 = *(const float4*)(g_r + ((size_t)((t * BB + b) * VV + vg)) * FF + h * DHH + dq * 4);
                    float4 res;
                    res.x = r4.x * __expf(acc.x * si);
                    res.y = r4.y * __expf(acc.y * si);
                    res.z = r4.z * __expf(acc.z * si);
                    res.w = r4.w * __expf(acc.w * si);
                    *(float4*)(g_pre + ((size_t)(t * BB + b)) * (VV * FF)
                               + h * (VV * DHH) + vg * DHH + dq * 4) = res;
                }
            }
            __syncthreads();   // pb consumed; sc free for next chunk
        }
    }
}

// ---------------- launch ----------------
extern "C" void kernel_launch(void* const* d_in, const int* in_sizes, int n_in,
                              void* d_out, int out_size)
{
    const float* vehicles    = (const float*)d_in[0];
    const float* initial_pos = (const float*)d_in[1];
    const float* lanes       = (const float*)d_in[2];
    const unsigned char* mask_lanes = (const unsigned char*)d_in[3];
    const float* Wk = (const float*)d_in[4];
    const float* bk = (const float*)d_in[5];
    const float* Wv = (const float*)d_in[6];
    const float* bv = (const float*)d_in[7];
    const float* Wq = (const float*)d_in[8];
    const float* bq = (const float*)d_in[9];
    const float* Wr = (const float*)d_in[10];
    const float* br = (const float*)d_in[11];
    const float* Wc = (const float*)d_in[12];
    const float* bc = (const float*)d_in[13];
    float* out = (float*)d_out;

    // prefer max shared-memory carveout so smem-heavy kernels co-reside
    cudaFuncSetAttribute(attn5_kernel,
                         cudaFuncAttributePreferredSharedMemoryCarveout,
                         cudaSharedmemCarveoutMaxShared);

    float *gK, *gLV, *gq, *gr, *gpre;
    cudaGetSymbolAddress((void**)&gK,   g_Kproj);
    cudaGetSymbolAddress((void**)&gLV,  g_LV);
    cudaGetSymbolAddress((void**)&gq,   g_q);
    cudaGetSymbolAddress((void**)&gr,   g_r);
    cudaGetSymbolAddress((void**)&gpre, g_pre);

    // 1) lane projections + mask
    lane_proj_kernel<false><<<BB * LL / 32, 256>>>(lanes, Wk, bk, gK);
    lane_proj_kernel<true ><<<BB * LL / 32, 256>>>(lanes, Wv, bv, gLV);
    mask_kernel<<<1, 256>>>(mask_lanes);

    // 2) fused q, r projections on v = vehicles + initial_pos
    gemm_qr_kernel<<<MROWS / 64, 256>>>(vehicles, initial_pos, Wq, bq, Wr, br, gq, gr);

    // 3) attention
    attn5_kernel<<<dim3(BB * HH, TT / TPB5), 256>>>();

    // 4) combine + residual: out = pre @ Wc^T + bc + vehicles - initial_pos
    gemm128_kernel<false, true><<<MROWS / 64, 256>>>(gpre, nullptr, Wc, bc, out, vehicles, initial_pos);
}

// round 11
// speedup vs baseline: 1.0719x; 1.0719x over previous
#include <cuda_runtime.h>
#include <math.h>

#define TT   30
#define BB   32
#define VV   32
#define FF   128
#define LL   256
#define LFF  64
#define HH   8
#define DHH  16
#define HISTN 10
#define MROWS (TT*BB*VV)   // 30720

typedef unsigned long long u64;

// ---- packed f32x2 helpers (sm_100+ PTX; per-lane IEEE fp32 FMA) ----
__device__ __forceinline__ u64 pk2(float a, float b) {
    u64 r; asm("mov.b64 %0,{%1,%2};" : "=l"(r) : "f"(a), "f"(b)); return r;
}
__device__ __forceinline__ float2 up2(u64 v) {
    float2 f; asm("mov.b64 {%0,%1},%2;" : "=f"(f.x), "=f"(f.y) : "l"(v)); return f;
}
__device__ __forceinline__ void fma2(u64& d, u64 a, u64 b) {
    asm("fma.rn.f32x2 %0,%1,%2,%0;" : "+l"(d) : "l"(a), "l"(b));
}

// ---------------- scratch (no allocations allowed) ----------------
__device__ float g_Kproj[BB*LL*FF];
__device__ float g_LV[BB*LL*FF];
__device__ unsigned char g_mask[BB*LL];
__device__ float g_q[MROWS*FF];
__device__ float g_r[MROWS*FF];
__device__ float g_pre[MROWS*FF];

// ---------------- lane projection ----------------
template<bool LOGSIG>
__global__ __launch_bounds__(256) void lane_proj_kernel(
    const float* __restrict__ lanes, const float* __restrict__ W,
    const float* __restrict__ bias, float* __restrict__ out)
{
    __shared__ float Wsh[LFF][FF + 1];
    __shared__ float lsh[32][LFF];
    __shared__ float bsh[FF];
    int tid = threadIdx.x;
    int row0 = blockIdx.x * 32;

    #pragma unroll
    for (int i = 0; i < 32; i++) {
        int idx = tid + i * 256;
        int f = idx >> 6, j = idx & 63;
        Wsh[j][f] = W[idx];
    }
    if (tid < FF) bsh[tid] = bias[tid];
    #pragma unroll
    for (int i = 0; i < 2; i++) {
        int idx = tid + i * 256;
        int r = idx >> 4;
        int c = (idx & 15) * 4;
        *(float4*)&lsh[r][c] = *(const float4*)(lanes + (size_t)(row0 + r) * LFF + c);
    }
    __syncthreads();

    int f = tid & 127;
    for (int r = tid >> 7; r < 32; r += 2) {
        float acc = bsh[f];
        #pragma unroll
        for (int j = 0; j < LFF; j++) acc += lsh[r][j] * Wsh[j][f];
        if (LOGSIG) {
            acc = (acc >= 0.f) ? -__logf(1.f + __expf(-acc))
                               : acc - __logf(1.f + __expf(acc));
        }
        out[(size_t)(row0 + r) * FF + f] = acc;
    }
}

// ---------------- mask: any over HIST, dtype self-detection ----------------
__global__ void mask_kernel(const unsigned char* __restrict__ m)
{
    int tid = threadIdx.x;
    const unsigned int* w = (const unsigned int*)m;
    bool okI = true, okF = true;
    for (int j = tid; j < (HISTN * BB * LL) / 4; j += 256) {
        unsigned int x = w[j];
        if (x > 1u) okI = false;
        if (x != 0u && x != 0x3F800000u) okF = false;
    }
    okI = __syncthreads_and((int)okI) != 0;
    okF = __syncthreads_and((int)okF) != 0;
    int cls = okI ? 0 : (okF ? 1 : 2);

    for (int i = tid; i < BB * LL; i += 256) {
        unsigned int any = 0;
        #pragma unroll
        for (int h = 0; h < HISTN; h++) {
            int j = h * BB * LL + i;
            unsigned int v;
            if (cls == 0)      v = w[j];
            else if (cls == 1) v = (w[j] != 0u);
            else               v = m[j];
            any |= v;
        }
        g_mask[i] = any ? 1 : 0;
    }
}

// ---------------- 30720x128x128 GEMM (packed f32x2) ----------------
template<bool SUM_AB, bool EPI>
__global__ __launch_bounds__(256) void gemm128_kernel(
    const float* __restrict__ A1, const float* __restrict__ A2,
    const float* __restrict__ W,  const float* __restrict__ bias,
    float* __restrict__ C,
    const float* __restrict__ E1, const float* __restrict__ E2)
{
    __shared__ float Ash[64][36];
    __shared__ float Wsh[32][132];
    int tid = threadIdx.x;
    int tx = tid & 31, ty = tid >> 5;
    int m0 = blockIdx.x * 64;

    u64 acc2[8][2];
    #pragma unroll
    for (int i = 0; i < 8; i++) { acc2[i][0] = 0ull; acc2[i][1] = 0ull; }

    for (int k0 = 0; k0 < 128; k0 += 32) {
        #pragma unroll
        for (int i = 0; i < 2; i++) {
            int idx = tid + i * 256;
            int row = idx >> 3, c = (idx & 7) * 4;
            float4 a = *(const float4*)(A1 + (size_t)(m0 + row) * FF + k0 + c);
            if (SUM_AB) {
                float4 b = *(const float4*)(A2 + (size_t)(m0 + row) * FF + k0 + c);
                a.x += b.x; a.y += b.y; a.z += b.z; a.w += b.w;
            }
            *(float4*)&Ash[row][c] = a;
        }
        #pragma unroll
        for (int i = 0; i < 16; i++) {
            int idx = tid + i * 256;
            int n = idx >> 5, kk = idx & 31;
            Wsh[kk][n] = W[n * FF + k0 + kk];
        }
        __syncthreads();
        #pragma unroll
        for (int k = 0; k < 32; k++) {
            ulonglong2 b2 = *(ulonglong2*)&Wsh[k][tx * 4];
            #pragma unroll
            for (int i = 0; i < 8; i++) {
                float a = Ash[ty * 8 + i][k];
                u64 a2 = pk2(a, a);
                fma2(acc2[i][0], a2, b2.x);
                fma2(acc2[i][1], a2, b2.y);
            }
        }
        __syncthreads();
    }

    int n = tx * 4;
    float4 bb = *(const float4*)(bias + n);
    #pragma unroll
    for (int i = 0; i < 8; i++) {
        int m = m0 + ty * 8 + i;
        float2 lo = up2(acc2[i][0]), hi = up2(acc2[i][1]);
        float4 o;
        o.x = lo.x + bb.x; o.y = lo.y + bb.y;
        o.z = hi.x + bb.z; o.w = hi.y + bb.w;
        if (EPI) {
            float4 e1 = *(const float4*)(E1 + (size_t)m * FF + n);
            float4 e2 = *(const float4*)(E2 + (size_t)m * FF + n);
            o.x += e1.x - e2.x; o.y += e1.y - e2.y;
            o.z += e1.z - e2.z; o.w += e1.w - e2.w;
        }
        *(float4*)(C + (size_t)m * FF + n) = o;
    }
}

// ---------------- fused q+r GEMM (packed f32x2) ----------------
__global__ __launch_bounds__(256, 2) void gemm_qr_kernel(
    const float* __restrict__ A1, const float* __restrict__ A2,
    const float* __restrict__ Wq, const float* __restrict__ bq,
    const float* __restrict__ Wr, const float* __restrict__ br,
    float* __restrict__ Cq, float* __restrict__ Cr)
{
    __shared__ float Ash[64][36];
    __shared__ float W1[32][132];
    __shared__ float W2[32][132];
    int tid = threadIdx.x;
    int tx = tid & 31, ty = tid >> 5;
    int m0 = blockIdx.x * 64;

    u64 aq[8][2], ar[8][2];
    #pragma unroll
    for (int i = 0; i < 8; i++) {
        aq[i][0] = aq[i][1] = 0ull;
        ar[i][0] = ar[i][1] = 0ull;
    }

    for (int k0 = 0; k0 < 128; k0 += 32) {
        #pragma unroll
        for (int i = 0; i < 2; i++) {
            int idx = tid + i * 256;
            int row = idx >> 3, c = (idx & 7) * 4;
            float4 a = *(const float4*)(A1 + (size_t)(m0 + row) * FF + k0 + c);
            float4 b = *(const float4*)(A2 + (size_t)(m0 + row) * FF + k0 + c);
            a.x += b.x; a.y += b.y; a.z += b.z; a.w += b.w;
            *(float4*)&Ash[row][c] = a;
        }
        #pragma unroll
        for (int i = 0; i < 16; i++) {
            int idx = tid + i * 256;
            int n = idx >> 5, kk = idx & 31;
            W1[kk][n] = Wq[n * FF + k0 + kk];
            W2[kk][n] = Wr[n * FF + k0 + kk];
        }
        __syncthreads();
        #pragma unroll
        for (int k = 0; k < 32; k++) {
            ulonglong2 q2 = *(ulonglong2*)&W1[k][tx * 4];
            ulonglong2 r2 = *(ulonglong2*)&W2[k][tx * 4];
            #pragma unroll
            for (int i = 0; i < 8; i++) {
                float a = Ash[ty * 8 + i][k];
                u64 a2 = pk2(a, a);
                fma2(aq[i][0], a2, q2.x);
                fma2(aq[i][1], a2, q2.y);
                fma2(ar[i][0], a2, r2.x);
                fma2(ar[i][1], a2, r2.y);
            }
        }
        __syncthreads();
    }

    int n = tx * 4;
    float4 bq4 = *(const float4*)(bq + n);
    float4 br4 = *(const float4*)(br + n);
    #pragma unroll
    for (int i = 0; i < 8; i++) {
        int m = m0 + ty * 8 + i;
        float2 qlo = up2(aq[i][0]), qhi = up2(aq[i][1]);
        float2 rlo = up2(ar[i][0]), rhi = up2(ar[i][1]);
        float4 oq, orr;
        oq.x  = qlo.x + bq4.x; oq.y  = qlo.y + bq4.y;
        oq.z  = qhi.x + bq4.z; oq.w  = qhi.y + bq4.w;
        orr.x = rlo.x + br4.x; orr.y = rlo.y + br4.y;
        orr.z = rhi.x + br4.z; orr.w = rhi.y + br4.w;
        *(float4*)(Cq + (size_t)m * FF + n) = oq;
        *(float4*)(Cr + (size_t)m * FF + n) = orr;
    }
}

// ---------------- attention v6: attn2 skeleton + broken dependency chains ----------------
#define TPB2 6
__global__ __launch_bounds__(256) void attn6_kernel()
{
    __shared__ float sc[32][260];       // scores -> unnormalized p (padded rows)
    __shared__ float lvsh[256][16];     // logsig(val) for this (b,h)
    __shared__ float qsh[32][16];
    __shared__ float sinv[32];
    __shared__ float pb[256][4];        // phase-B partials

    int tid = threadIdx.x;
    int b = blockIdx.x >> 3, h = blockIdx.x & 7;
    int t0 = blockIdx.y * TPB2;
    int l = tid;
    int warp = tid >> 5, lane = tid & 31;

    // K row for this l in registers
    float4 k0, k1, k2, k3;
    {
        const float* kp = g_Kproj + ((size_t)(b * LL + l)) * FF + h * DHH;
        k0 = *(const float4*)(kp);
        k1 = *(const float4*)(kp + 4);
        k2 = *(const float4*)(kp + 8);
        k3 = *(const float4*)(kp + 12);
        const float* lvp = g_LV + ((size_t)(b * LL + l)) * FF + h * DHH;
        #pragma unroll
        for (int i = 0; i < 4; i++)
            *(float4*)&lvsh[l][i * 4] = *(const float4*)(lvp + i * 4);
    }
    bool mon = g_mask[b * LL + l] != 0;

    // phase-B thread mapping: tid = vB*8 + half*4 + dq
    int dq = tid & 3;            // d quad
    int half = (tid >> 2) & 1;   // l parity
    int vB = tid >> 3;           // v row 0..31

    for (int t = t0; t < t0 + TPB2; t++) {
        __syncthreads();                 // protect qsh/sc/sinv reuse
        if (tid < 128) {                 // load q tile [32,16] as float4
            int v = tid >> 2, q4 = tid & 3;
            *(float4*)&qsh[v][q4 * 4] =
                *(const float4*)(g_q + ((size_t)((t * BB + b) * VV + v)) * FF + h * DHH + q4 * 4);
        }
        __syncthreads();

        // ---- Phase A: 4 independent 4-FMA partials per v (tree combine) ----
        #pragma unroll
        for (int v = 0; v < 32; v++) {
            float4 q0 = *(float4*)&qsh[v][0];
            float4 q1 = *(float4*)&qsh[v][4];
            float4 q2 = *(float4*)&qsh[v][8];
            float4 q3 = *(float4*)&qsh[v][12];
            float p0 = q0.x * k0.x; p0 = fmaf(q0.y, k0.y, p0);
            p0 = fmaf(q0.z, k0.z, p0); p0 = fmaf(q0.w, k0.w, p0);
            float p1 = q1.x * k1.x; p1 = fmaf(q1.y, k1.y, p1);
            p1 = fmaf(q1.z, k1.z, p1); p1 = fmaf(q1.w, k1.w, p1);
            float p2 = q2.x * k2.x; p2 = fmaf(q2.y, k2.y, p2);
            p2 = fmaf(q2.z, k2.z, p2); p2 = fmaf(q2.w, k2.w, p2);
            float p3 = q3.x * k3.x; p3 = fmaf(q3.y, k3.y, p3);
            p3 = fmaf(q3.z, k3.z, p3); p3 = fmaf(q3.w, k3.w, p3);
            float s = (p0 + p1) + (p2 + p3);
            sc[v][l] = mon ? (s * 0.25f) : -1e9f;
        }
        __syncthreads();

        // ---- softmax over l (rows = v): warp handles rows warp, warp+8, +16, +24 ----
        #pragma unroll
        for (int rr = 0; rr < 4; rr++) {
            int rv = warp + rr * 8;
            float4 a = *(float4*)&sc[rv][lane * 8];
            float4 c = *(float4*)&sc[rv][lane * 8 + 4];
            float mx = fmaxf(fmaxf(fmaxf(a.x, a.y), fmaxf(a.z, a.w)),
                             fmaxf(fmaxf(c.x, c.y), fmaxf(c.z, c.w)));
            #pragma unroll
            for (int o = 16; o > 0; o >>= 1)
                mx = fmaxf(mx, __shfl_xor_sync(0xffffffffu, mx, o));
            a.x = __expf(a.x - mx); a.y = __expf(a.y - mx);
            a.z = __expf(a.z - mx); a.w = __expf(a.w - mx);
            c.x = __expf(c.x - mx); c.y = __expf(c.y - mx);
            c.z = __expf(c.z - mx); c.w = __expf(c.w - mx);
            float sm = ((a.x + a.y) + (a.z + a.w)) + ((c.x + c.y) + (c.z + c.w));
            #pragma unroll
            for (int o = 16; o > 0; o >>= 1)
                sm += __shfl_xor_sync(0xffffffffu, sm, o);
            *(float4*)&sc[rv][lane * 8] = a;
            *(float4*)&sc[rv][lane * 8 + 4] = c;
            if (lane == 0) sinv[rv] = __fdividef(1.f, sm);
        }
        __syncthreads();

        // ---- Phase B: 4 independent accumulators per component (chains of 32) ----
        {
            float4 a0 = make_float4(0.f,0.f,0.f,0.f);
            float4 a1 = make_float4(0.f,0.f,0.f,0.f);
            float4 a2 = make_float4(0.f,0.f,0.f,0.f);
            float4 a3 = make_float4(0.f,0.f,0.f,0.f);
            #pragma unroll 4
            for (int g = 0; g < 32; g++) {
                int base = 8 * g + half;
                float p; float4 lv;
                p = sc[vB][base];     lv = *(float4*)&lvsh[base][dq * 4];
                a0.x = fmaf(p, lv.x, a0.x); a0.y = fmaf(p, lv.y, a0.y);
                a0.z = fmaf(p, lv.z, a0.z); a0.w = fmaf(p, lv.w, a0.w);
                p = sc[vB][base + 2]; lv = *(float4*)&lvsh[base + 2][dq * 4];
                a1.x = fmaf(p, lv.x, a1.x); a1.y = fmaf(p, lv.y, a1.y);
                a1.z = fmaf(p, lv.z, a1.z); a1.w = fmaf(p, lv.w, a1.w);
                p = sc[vB][base + 4]; lv = *(float4*)&lvsh[base + 4][dq * 4];
                a2.x = fmaf(p, lv.x, a2.x); a2.y = fmaf(p, lv.y, a2.y);
                a2.z = fmaf(p, lv.z, a2.z); a2.w = fmaf(p, lv.w, a2.w);
                p = sc[vB][base + 6]; lv = *(float4*)&lvsh[base + 6][dq * 4];
                a3.x = fmaf(p, lv.x, a3.x); a3.y = fmaf(p, lv.y, a3.y);
                a3.z = fmaf(p, lv.z, a3.z); a3.w = fmaf(p, lv.w, a3.w);
            }
            float4 acc;
            acc.x = (a0.x + a1.x) + (a2.x + a3.x);
            acc.y = (a0.y + a1.y) + (a2.y + a3.y);
            acc.z = (a0.z + a1.z) + (a2.z + a3.z);
            acc.w = (a0.w + a1.w) + (a2.w + a3.w);
            *(float4*)&pb[tid][0] = acc;
            __syncthreads();
            if (half == 0) {
                float4 o = *(float4*)&pb[tid ^ 4][0];
                o.x += acc.x; o.y += acc.y; o.z += acc.z; o.w += acc.w;
                float si = sinv[vB];
                float4 r4 = *(const float4*)(g_r + ((size_t)((t * BB + b) * VV + vB)) * FF + h * DHH + dq * 4);
                float4 res;
                res.x = r4.x * __expf(o.x * si);
                res.y = r4.y * __expf(o.y * si);
                res.z = r4.z * __expf(o.z * si);
                res.w = r4.w * __expf(o.w * si);
                *(float4*)(g_pre + ((size_t)(t * BB + b)) * (VV * FF)
                           + h * (VV * DHH) + vB * DHH + dq * 4) = res;
            }
        }
    }
}

// ---------------- launch ----------------
extern "C" void kernel_launch(void* const* d_in, const int* in_sizes, int n_in,
                              void* d_out, int out_size)
{
    const float* vehicles    = (const float*)d_in[0];
    const float* initial_pos = (const float*)d_in[1];
    const float* lanes       = (const float*)d_in[2];
    const unsigned char* mask_lanes = (const unsigned char*)d_in[3];
    const float* Wk = (const float*)d_in[4];
    const float* bk = (const float*)d_in[5];
    const float* Wv = (const float*)d_in[6];
    const float* bv = (const float*)d_in[7];
    const float* Wq = (const float*)d_in[8];
    const float* bq = (const float*)d_in[9];
    const float* Wr = (const float*)d_in[10];
    const float* br = (const float*)d_in[11];
    const float* Wc = (const float*)d_in[12];
    const float* bc = (const float*)d_in[13];
    float* out = (float*)d_out;

    cudaFuncSetAttribute(attn6_kernel,
                         cudaFuncAttributePreferredSharedMemoryCarveout,
                         cudaSharedmemCarveoutMaxShared);

    float *gK, *gLV, *gq, *gr, *gpre;
    cudaGetSymbolAddress((void**)&gK,   g_Kproj);
    cudaGetSymbolAddress((void**)&gLV,  g_LV);
    cudaGetSymbolAddress((void**)&gq,   g_q);
    cudaGetSymbolAddress((void**)&gr,   g_r);
    cudaGetSymbolAddress((void**)&gpre, g_pre);

    // 1) lane projections + mask
    lane_proj_kernel<false><<<BB * LL / 32, 256>>>(lanes, Wk, bk, gK);
    lane_proj_kernel<true ><<<BB * LL / 32, 256>>>(lanes, Wv, bv, gLV);
    mask_kernel<<<1, 256>>>(mask_lanes);

    // 2) fused q, r projections on v = vehicles + initial_pos
    gemm_qr_kernel<<<MROWS / 64, 256>>>(vehicles, initial_pos, Wq, bq, Wr, br, gq, gr);

    // 3) attention
    attn6_kernel<<<dim3(BB * HH, TT / TPB2), 256>>>();

    // 4) combine + residual: out = pre @ Wc^T + bc + vehicles - initial_pos
    gemm128_kernel<false, true><<<MROWS / 64, 256>>>(gpre, nullptr, Wc, bc, out, vehicles, initial_pos);
}

// round 12
// speedup vs baseline: 1.4622x; 1.3642x over previous
#include <cuda_runtime.h>
#include <math.h>

#define TT   30
#define BB   32
#define VV   32
#define FF   128
#define LL   256
#define LFF  64
#define HH   8
#define DHH  16
#define HISTN 10
#define MROWS (TT*BB*VV)   // 30720

typedef unsigned long long u64;

// ---- packed f32x2 helpers (GEMMs only) ----
__device__ __forceinline__ u64 pk2(float a, float b) {
    u64 r; asm("mov.b64 %0,{%1,%2};" : "=l"(r) : "f"(a), "f"(b)); return r;
}
__device__ __forceinline__ float2 up2(u64 v) {
    float2 f; asm("mov.b64 {%0,%1},%2;" : "=f"(f.x), "=f"(f.y) : "l"(v)); return f;
}
__device__ __forceinline__ void fma2(u64& d, u64 a, u64 b) {
    asm("fma.rn.f32x2 %0,%1,%2,%0;" : "+l"(d) : "l"(a), "l"(b));
}

// ---- tf32 mma helpers ----
__device__ __forceinline__ unsigned tf32u(float x) {
    unsigned u; asm("cvt.rna.tf32.f32 %0,%1;" : "=r"(u) : "f"(x)); return u;
}
__device__ __forceinline__ void mma_tf32(float* c, const unsigned* a, unsigned b0, unsigned b1) {
    asm volatile("mma.sync.aligned.m16n8k8.row.col.f32.tf32.tf32.f32 "
        "{%0,%1,%2,%3},{%4,%5,%6,%7},{%8,%9},{%0,%1,%2,%3};"
        : "+f"(c[0]), "+f"(c[1]), "+f"(c[2]), "+f"(c[3])
        : "r"(a[0]), "r"(a[1]), "r"(a[2]), "r"(a[3]), "r"(b0), "r"(b1));
}

// ---------------- scratch ----------------
__device__ float g_Kproj[BB*LL*FF];
__device__ float g_LV[BB*LL*FF];
__device__ unsigned char g_mask[BB*LL];
__device__ float g_q[MROWS*FF];
__device__ float g_r[MROWS*FF];
__device__ float g_pre[MROWS*FF];

// ---------------- lane projection ----------------
template<bool LOGSIG>
__global__ __launch_bounds__(256) void lane_proj_kernel(
    const float* __restrict__ lanes, const float* __restrict__ W,
    const float* __restrict__ bias, float* __restrict__ out)
{
    __shared__ float Wsh[LFF][FF + 1];
    __shared__ float lsh[32][LFF];
    __shared__ float bsh[FF];
    int tid = threadIdx.x;
    int row0 = blockIdx.x * 32;

    #pragma unroll
    for (int i = 0; i < 32; i++) {
        int idx = tid + i * 256;
        int f = idx >> 6, j = idx & 63;
        Wsh[j][f] = W[idx];
    }
    if (tid < FF) bsh[tid] = bias[tid];
    #pragma unroll
    for (int i = 0; i < 2; i++) {
        int idx = tid + i * 256;
        int r = idx >> 4;
        int c = (idx & 15) * 4;
        *(float4*)&lsh[r][c] = *(const float4*)(lanes + (size_t)(row0 + r) * LFF + c);
    }
    __syncthreads();

    int f = tid & 127;
    for (int r = tid >> 7; r < 32; r += 2) {
        float acc = bsh[f];
        #pragma unroll
        for (int j = 0; j < LFF; j++) acc += lsh[r][j] * Wsh[j][f];
        if (LOGSIG) {
            acc = (acc >= 0.f) ? -__logf(1.f + __expf(-acc))
                               : acc - __logf(1.f + __expf(acc));
        }
        out[(size_t)(row0 + r) * FF + f] = acc;
    }
}

// ---------------- mask ----------------
__global__ void mask_kernel(const unsigned char* __restrict__ m)
{
    int tid = threadIdx.x;
    const unsigned int* w = (const unsigned int*)m;
    bool okI = true, okF = true;
    for (int j = tid; j < (HISTN * BB * LL) / 4; j += 256) {
        unsigned int x = w[j];
        if (x > 1u) okI = false;
        if (x != 0u && x != 0x3F800000u) okF = false;
    }
    okI = __syncthreads_and((int)okI) != 0;
    okF = __syncthreads_and((int)okF) != 0;
    int cls = okI ? 0 : (okF ? 1 : 2);

    for (int i = tid; i < BB * LL; i += 256) {
        unsigned int any = 0;
        #pragma unroll
        for (int h = 0; h < HISTN; h++) {
            int j = h * BB * LL + i;
            unsigned int v;
            if (cls == 0)      v = w[j];
            else if (cls == 1) v = (w[j] != 0u);
            else               v = m[j];
            any |= v;
        }
        g_mask[i] = any ? 1 : 0;
    }
}

// ---------------- 30720x128x128 GEMM (packed f32x2) ----------------
template<bool SUM_AB, bool EPI>
__global__ __launch_bounds__(256) void gemm128_kernel(
    const float* __restrict__ A1, const float* __restrict__ A2,
    const float* __restrict__ W,  const float* __restrict__ bias,
    float* __restrict__ C,
    const float* __restrict__ E1, const float* __restrict__ E2)
{
    __shared__ float Ash[64][36];
    __shared__ float Wsh[32][132];
    int tid = threadIdx.x;
    int tx = tid & 31, ty = tid >> 5;
    int m0 = blockIdx.x * 64;

    u64 acc2[8][2];
    #pragma unroll
    for (int i = 0; i < 8; i++) { acc2[i][0] = 0ull; acc2[i][1] = 0ull; }

    for (int k0 = 0; k0 < 128; k0 += 32) {
        #pragma unroll
        for (int i = 0; i < 2; i++) {
            int idx = tid + i * 256;
            int row = idx >> 3, c = (idx & 7) * 4;
            float4 a = *(const float4*)(A1 + (size_t)(m0 + row) * FF + k0 + c);
            if (SUM_AB) {
                float4 b = *(const float4*)(A2 + (size_t)(m0 + row) * FF + k0 + c);
                a.x += b.x; a.y += b.y; a.z += b.z; a.w += b.w;
            }
            *(float4*)&Ash[row][c] = a;
        }
        #pragma unroll
        for (int i = 0; i < 16; i++) {
            int idx = tid + i * 256;
            int n = idx >> 5, kk = idx & 31;
            Wsh[kk][n] = W[n * FF + k0 + kk];
        }
        __syncthreads();
        #pragma unroll
        for (int k = 0; k < 32; k++) {
            ulonglong2 b2 = *(ulonglong2*)&Wsh[k][tx * 4];
            #pragma unroll
            for (int i = 0; i < 8; i++) {
                float a = Ash[ty * 8 + i][k];
                u64 a2 = pk2(a, a);
                fma2(acc2[i][0], a2, b2.x);
                fma2(acc2[i][1], a2, b2.y);
            }
        }
        __syncthreads();
    }

    int n = tx * 4;
    float4 bb = *(const float4*)(bias + n);
    #pragma unroll
    for (int i = 0; i < 8; i++) {
        int m = m0 + ty * 8 + i;
        float2 lo = up2(acc2[i][0]), hi = up2(acc2[i][1]);
        float4 o;
        o.x = lo.x + bb.x; o.y = lo.y + bb.y;
        o.z = hi.x + bb.z; o.w = hi.y + bb.w;
        if (EPI) {
            float4 e1 = *(const float4*)(E1 + (size_t)m * FF + n);
            float4 e2 = *(const float4*)(E2 + (size_t)m * FF + n);
            o.x += e1.x - e2.x; o.y += e1.y - e2.y;
            o.z += e1.z - e2.z; o.w += e1.w - e2.w;
        }
        *(float4*)(C + (size_t)m * FF + n) = o;
    }
}

// ---------------- fused q+r GEMM (packed f32x2) ----------------
__global__ __launch_bounds__(256, 2) void gemm_qr_kernel(
    const float* __restrict__ A1, const float* __restrict__ A2,
    const float* __restrict__ Wq, const float* __restrict__ bq,
    const float* __restrict__ Wr, const float* __restrict__ br,
    float* __restrict__ Cq, float* __restrict__ Cr)
{
    __shared__ float Ash[64][36];
    __shared__ float W1[32][132];
    __shared__ float W2[32][132];
    int tid = threadIdx.x;
    int tx = tid & 31, ty = tid >> 5;
    int m0 = blockIdx.x * 64;

    u64 aq[8][2], ar[8][2];
    #pragma unroll
    for (int i = 0; i < 8; i++) {
        aq[i][0] = aq[i][1] = 0ull;
        ar[i][0] = ar[i][1] = 0ull;
    }

    for (int k0 = 0; k0 < 128; k0 += 32) {
        #pragma unroll
        for (int i = 0; i < 2; i++) {
            int idx = tid + i * 256;
            int row = idx >> 3, c = (idx & 7) * 4;
            float4 a = *(const float4*)(A1 + (size_t)(m0 + row) * FF + k0 + c);
            float4 b = *(const float4*)(A2 + (size_t)(m0 + row) * FF + k0 + c);
            a.x += b.x; a.y += b.y; a.z += b.z; a.w += b.w;
            *(float4*)&Ash[row][c] = a;
        }
        #pragma unroll
        for (int i = 0; i < 16; i++) {
            int idx = tid + i * 256;
            int n = idx >> 5, kk = idx & 31;
            W1[kk][n] = Wq[n * FF + k0 + kk];
            W2[kk][n] = Wr[n * FF + k0 + kk];
        }
        __syncthreads();
        #pragma unroll
        for (int k = 0; k < 32; k++) {
            ulonglong2 q2 = *(ulonglong2*)&W1[k][tx * 4];
            ulonglong2 r2 = *(ulonglong2*)&W2[k][tx * 4];
            #pragma unroll
            for (int i = 0; i < 8; i++) {
                float a = Ash[ty * 8 + i][k];
                u64 a2 = pk2(a, a);
                fma2(aq[i][0], a2, q2.x);
                fma2(aq[i][1], a2, q2.y);
                fma2(ar[i][0], a2, r2.x);
                fma2(ar[i][1], a2, r2.y);
            }
        }
        __syncthreads();
    }

    int n = tx * 4;
    float4 bq4 = *(const float4*)(bq + n);
    float4 br4 = *(const float4*)(br + n);
    #pragma unroll
    for (int i = 0; i < 8; i++) {
        int m = m0 + ty * 8 + i;
        float2 qlo = up2(aq[i][0]), qhi = up2(aq[i][1]);
        float2 rlo = up2(ar[i][0]), rhi = up2(ar[i][1]);
        float4 oq, orr;
        oq.x  = qlo.x + bq4.x; oq.y  = qlo.y + bq4.y;
        oq.z  = qhi.x + bq4.z; oq.w  = qhi.y + bq4.w;
        orr.x = rlo.x + br4.x; orr.y = rlo.y + br4.y;
        orr.z = rhi.x + br4.z; orr.w = rhi.y + br4.w;
        *(float4*)(Cq + (size_t)m * FF + n) = oq;
        *(float4*)(Cr + (size_t)m * FF + n) = orr;
    }
}

// ---------------- attention v7: tensor-core (mma.sync tf32) ----------------
// One block per (b,h), all 30 t. Dynamic smem layout (floats):
//   Ksh  [256][20]  tf32     @ 0      (5120)
//   LVsh [256][24]  tf32     @ 5120   (6144)
//   qsh  [32][20]   tf32     @ 11264  (640)
//   sc   [32][260]  f32      @ 11904  (8320)
//   pb   [8][520]   f32      @ 20224  (4160)
//   sinv [32]                @ 24384
//   msk  [256]               @ 24416
#define AOFF_K   0
#define AOFF_LV  5120
#define AOFF_Q   11264
#define AOFF_SC  11904
#define AOFF_PB  20224
#define AOFF_SI  24384
#define AOFF_M   24416
#define ASMEM_FLOATS 24672
#define ASMEM_BYTES  (ASMEM_FLOATS * 4)

__global__ __launch_bounds__(256) void attn7_kernel()
{
    extern __shared__ float smp[];
    float* Ksh  = smp + AOFF_K;
    float* LVsh = smp + AOFF_LV;
    float* qsh  = smp + AOFF_Q;
    float* sc   = smp + AOFF_SC;
    float* pb   = smp + AOFF_PB;
    float* sinv = smp + AOFF_SI;
    float* msk  = smp + AOFF_M;

    int tid = threadIdx.x;
    int b = blockIdx.x >> 3, h = blockIdx.x & 7;
    int w = tid >> 5, lane = tid & 31;
    int qr = lane >> 2, qc = lane & 3;   // quad row / col within warp

    // ---- per-block init: K, LV (tf32-converted), mask ----
    {
        int l = tid;
        const float* kp = g_Kproj + ((size_t)(b * LL + l)) * FF + h * DHH;
        const float* lvp = g_LV + ((size_t)(b * LL + l)) * FF + h * DHH;
        #pragma unroll
        for (int i = 0; i < 4; i++) {
            float4 kv = *(const float4*)(kp + i * 4);
            Ksh[l * 20 + i * 4 + 0] = __uint_as_float(tf32u(kv.x));
            Ksh[l * 20 + i * 4 + 1] = __uint_as_float(tf32u(kv.y));
            Ksh[l * 20 + i * 4 + 2] = __uint_as_float(tf32u(kv.z));
            Ksh[l * 20 + i * 4 + 3] = __uint_as_float(tf32u(kv.w));
            float4 lv = *(const float4*)(lvp + i * 4);
            LVsh[l * 24 + i * 4 + 0] = __uint_as_float(tf32u(lv.x));
            LVsh[l * 24 + i * 4 + 1] = __uint_as_float(tf32u(lv.y));
            LVsh[l * 24 + i * 4 + 2] = __uint_as_float(tf32u(lv.z));
            LVsh[l * 24 + i * 4 + 3] = __uint_as_float(tf32u(lv.w));
        }
        msk[l] = g_mask[b * LL + l] ? 1.f : 0.f;
    }

    for (int t = 0; t < TT; t++) {
        __syncthreads();
        // ---- q tile load + tf32 convert ----
        if (tid < 128) {
            int v = tid >> 2, c4 = (tid & 3) * 4;
            float4 qv = *(const float4*)(g_q + ((size_t)((t * BB + b) * VV + v)) * FF + h * DHH + c4);
            qsh[v * 20 + c4 + 0] = __uint_as_float(tf32u(qv.x));
            qsh[v * 20 + c4 + 1] = __uint_as_float(tf32u(qv.y));
            qsh[v * 20 + c4 + 2] = __uint_as_float(tf32u(qv.z));
            qsh[v * 20 + c4 + 3] = __uint_as_float(tf32u(qv.w));
        }
        __syncthreads();

        // ---- Stage A: scores[32,256] = q @ K^T ; warp w owns n in [w*32, w*32+32) ----
        {
            unsigned Aq[2][2][4];
            #pragma unroll
            for (int mi = 0; mi < 2; mi++)
                #pragma unroll
                for (int ki = 0; ki < 2; ki++) {
                    int r = mi * 16 + qr;
                    Aq[mi][ki][0] = __float_as_uint(qsh[r * 20 + ki * 8 + qc]);
                    Aq[mi][ki][1] = __float_as_uint(qsh[(r + 8) * 20 + ki * 8 + qc]);
                    Aq[mi][ki][2] = __float_as_uint(qsh[r * 20 + ki * 8 + qc + 4]);
                    Aq[mi][ki][3] = __float_as_uint(qsh[(r + 8) * 20 + ki * 8 + qc + 4]);
                }
            float Cs[2][4][4];
            #pragma unroll
            for (int mi = 0; mi < 2; mi++)
                #pragma unroll
                for (int ni = 0; ni < 4; ni++)
                    #pragma unroll
                    for (int j = 0; j < 4; j++) Cs[mi][ni][j] = 0.f;

            #pragma unroll
            for (int ni = 0; ni < 4; ni++) {
                int n0 = w * 32 + ni * 8;
                unsigned b00 = __float_as_uint(Ksh[(n0 + qr) * 20 + qc]);
                unsigned b01 = __float_as_uint(Ksh[(n0 + qr) * 20 + qc + 4]);
                unsigned b10 = __float_as_uint(Ksh[(n0 + qr) * 20 + 8 + qc]);
                unsigned b11 = __float_as_uint(Ksh[(n0 + qr) * 20 + 8 + qc + 4]);
                #pragma unroll
                for (int mi = 0; mi < 2; mi++) {
                    mma_tf32(Cs[mi][ni], Aq[mi][0], b00, b01);
                    mma_tf32(Cs[mi][ni], Aq[mi][1], b10, b11);
                }
            }
            // mask + scale + store to sc
            #pragma unroll
            for (int mi = 0; mi < 2; mi++)
                #pragma unroll
                for (int ni = 0; ni < 4; ni++) {
                    int v = mi * 16 + qr;
                    int n = w * 32 + ni * 8 + 2 * qc;
                    float m0 = msk[n], m1 = msk[n + 1];
                    float2 s01, s23;
                    s01.x = (m0 != 0.f) ? Cs[mi][ni][0] * 0.25f : -1e9f;
                    s01.y = (m1 != 0.f) ? Cs[mi][ni][1] * 0.25f : -1e9f;
                    s23.x = (m0 != 0.f) ? Cs[mi][ni][2] * 0.25f : -1e9f;
                    s23.y = (m1 != 0.f) ? Cs[mi][ni][3] * 0.25f : -1e9f;
                    *(float2*)&sc[v * 260 + n] = s01;
                    *(float2*)&sc[(v + 8) * 260 + n] = s23;
                }
        }
        __syncthreads();

        // ---- softmax over l (rows = v): warp handles rows w, w+8, w+16, w+24 ----
        #pragma unroll
        for (int rr = 0; rr < 4; rr++) {
            int rv = w + rr * 8;
            float4 a = *(float4*)&sc[rv * 260 + lane * 8];
            float4 c = *(float4*)&sc[rv * 260 + lane * 8 + 4];
            float mx = fmaxf(fmaxf(fmaxf(a.x, a.y), fmaxf(a.z, a.w)),
                             fmaxf(fmaxf(c.x, c.y), fmaxf(c.z, c.w)));
            #pragma unroll
            for (int o = 16; o > 0; o >>= 1)
                mx = fmaxf(mx, __shfl_xor_sync(0xffffffffu, mx, o));
            a.x = __expf(a.x - mx); a.y = __expf(a.y - mx);
            a.z = __expf(a.z - mx); a.w = __expf(a.w - mx);
            c.x = __expf(c.x - mx); c.y = __expf(c.y - mx);
            c.z = __expf(c.z - mx); c.w = __expf(c.w - mx);
            float sm = ((a.x + a.y) + (a.z + a.w)) + ((c.x + c.y) + (c.z + c.w));
            #pragma unroll
            for (int o = 16; o > 0; o >>= 1)
                sm += __shfl_xor_sync(0xffffffffu, sm, o);
            *(float4*)&sc[rv * 260 + lane * 8] = a;
            *(float4*)&sc[rv * 260 + lane * 8 + 4] = c;
            if (lane == 0) sinv[rv] = __fdividef(1.f, sm);
        }
        __syncthreads();

        // ---- Stage B: out[32,16] = p @ LV ; warp w owns k in [w*32, w*32+32) ----
        {
            float Co[2][2][4];
            #pragma unroll
            for (int mi = 0; mi < 2; mi++)
                #pragma unroll
                for (int ni = 0; ni < 2; ni++)
                    #pragma unroll
                    for (int j = 0; j < 4; j++) Co[mi][ni][j] = 0.f;

            #pragma unroll
            for (int ki = 0; ki < 4; ki++) {
                int kk = w * 32 + ki * 8;
                unsigned Ap[2][4];
                #pragma unroll
                for (int mi = 0; mi < 2; mi++) {
                    int r = mi * 16 + qr;
                    Ap[mi][0] = tf32u(sc[r * 260 + kk + qc]);
                    Ap[mi][1] = tf32u(sc[(r + 8) * 260 + kk + qc]);
                    Ap[mi][2] = tf32u(sc[r * 260 + kk + qc + 4]);
                    Ap[mi][3] = tf32u(sc[(r + 8) * 260 + kk + qc + 4]);
                }
                #pragma unroll
                for (int ni = 0; ni < 2; ni++) {
                    int d0 = ni * 8;
                    unsigned b0 = __float_as_uint(LVsh[(kk + qc) * 24 + d0 + qr]);
                    unsigned b1 = __float_as_uint(LVsh[(kk + qc + 4) * 24 + d0 + qr]);
                    #pragma unroll
                    for (int mi = 0; mi < 2; mi++)
                        mma_tf32(Co[mi][ni], Ap[mi], b0, b1);
                }
            }
            // store partials to pb[w]
            #pragma unroll
            for (int mi = 0; mi < 2; mi++)
                #pragma unroll
                for (int ni = 0; ni < 2; ni++) {
                    int v = mi * 16 + qr;
                    int d = ni * 8 + 2 * qc;
                    float2 p01, p23;
                    p01.x = Co[mi][ni][0]; p01.y = Co[mi][ni][1];
                    p23.x = Co[mi][ni][2]; p23.y = Co[mi][ni][3];
                    *(float2*)&pb[w * 520 + v * 16 + d] = p01;
                    *(float2*)&pb[w * 520 + (v + 8) * 16 + d] = p23;
                }
        }
        __syncthreads();

        // ---- cross-warp reduce (8 partials) + exp epilogue ----
        {
            int v = tid >> 3;
            int d = (tid & 7) * 2;
            float2 s = make_float2(0.f, 0.f);
            #pragma unroll
            for (int ww = 0; ww < 8; ww++) {
                float2 p = *(float2*)&pb[ww * 520 + tid * 2];
                s.x += p.x; s.y += p.y;
            }
            float si = sinv[v];
            float2 r2 = *(const float2*)(g_r + ((size_t)((t * BB + b) * VV + v)) * FF + h * DHH + d);
            float2 res;
            res.x = r2.x * __expf(s.x * si);
            res.y = r2.y * __expf(s.y * si);
            *(float2*)(g_pre + ((size_t)(t * BB + b)) * (VV * FF)
                       + h * (VV * DHH) + v * DHH + d) = res;
        }
    }
}

// ---------------- launch ----------------
extern "C" void kernel_launch(void* const* d_in, const int* in_sizes, int n_in,
                              void* d_out, int out_size)
{
    const float* vehicles    = (const float*)d_in[0];
    const float* initial_pos = (const float*)d_in[1];
    const float* lanes       = (const float*)d_in[2];
    const unsigned char* mask_lanes = (const unsigned char*)d_in[3];
    const float* Wk = (const float*)d_in[4];
    const float* bk = (const float*)d_in[5];
    const float* Wv = (const float*)d_in[6];
    const float* bv = (const float*)d_in[7];
    const float* Wq = (const float*)d_in[8];
    const float* bq = (const float*)d_in[9];
    const float* Wr = (const float*)d_in[10];
    const float* br = (const float*)d_in[11];
    const float* Wc = (const float*)d_in[12];
    const float* bc = (const float*)d_in[13];
    float* out = (float*)d_out;

    cudaFuncSetAttribute(attn7_kernel,
                         cudaFuncAttributeMaxDynamicSharedMemorySize, ASMEM_BYTES);
    cudaFuncSetAttribute(attn7_kernel,
                         cudaFuncAttributePreferredSharedMemoryCarveout,
                         cudaSharedmemCarveoutMaxShared);

    float *gK, *gLV, *gq, *gr, *gpre;
    cudaGetSymbolAddress((void**)&gK,   g_Kproj);
    cudaGetSymbolAddress((void**)&gLV,  g_LV);
    cudaGetSymbolAddress((void**)&gq,   g_q);
    cudaGetSymbolAddress((void**)&gr,   g_r);
    cudaGetSymbolAddress((void**)&gpre, g_pre);

    // 1) lane projections + mask
    lane_proj_kernel<false><<<BB * LL / 32, 256>>>(lanes, Wk, bk, gK);
    lane_proj_kernel<true ><<<BB * LL / 32, 256>>>(lanes, Wv, bv, gLV);
    mask_kernel<<<1, 256>>>(mask_lanes);

    // 2) fused q, r projections on v = vehicles + initial_pos
    gemm_qr_kernel<<<MROWS / 64, 256>>>(vehicles, initial_pos, Wq, bq, Wr, br, gq, gr);

    // 3) attention (tensor cores)
    attn7_kernel<<<BB * HH, 256, ASMEM_BYTES>>>();

    // 4) combine + residual: out = pre @ Wc^T + bc + vehicles - initial_pos
    gemm128_kernel<false, true><<<MROWS / 64, 256>>>(gpre, nullptr, Wc, bc, out, vehicles, initial_pos);
}

// round 13
// speedup vs baseline: 1.5840x; 1.0833x over previous
#include <cuda_runtime.h>
#include <math.h>

#define TT   30
#define BB   32
#define VV   32
#define FF   128
#define LL   256
#define LFF  64
#define HH   8
#define DHH  16
#define HISTN 10
#define MROWS (TT*BB*VV)   // 30720

typedef unsigned long long u64;

// ---- packed f32x2 helpers (GEMMs only) ----
__device__ __forceinline__ u64 pk2(float a, float b) {
    u64 r; asm("mov.b64 %0,{%1,%2};" : "=l"(r) : "f"(a), "f"(b)); return r;
}
__device__ __forceinline__ float2 up2(u64 v) {
    float2 f; asm("mov.b64 {%0,%1},%2;" : "=f"(f.x), "=f"(f.y) : "l"(v)); return f;
}
__device__ __forceinline__ void fma2(u64& d, u64 a, u64 b) {
    asm("fma.rn.f32x2 %0,%1,%2,%0;" : "+l"(d) : "l"(a), "l"(b));
}

// ---- tf32 mma helpers ----
__device__ __forceinline__ unsigned tf32u(float x) {
    unsigned u; asm("cvt.rna.tf32.f32 %0,%1;" : "=r"(u) : "f"(x)); return u;
}
__device__ __forceinline__ void mma_tf32(float* c, const unsigned* a, unsigned b0, unsigned b1) {
    asm volatile("mma.sync.aligned.m16n8k8.row.col.f32.tf32.tf32.f32 "
        "{%0,%1,%2,%3},{%4,%5,%6,%7},{%8,%9},{%0,%1,%2,%3};"
        : "+f"(c[0]), "+f"(c[1]), "+f"(c[2]), "+f"(c[3])
        : "r"(a[0]), "r"(a[1]), "r"(a[2]), "r"(a[3]), "r"(b0), "r"(b1));
}

// ---------------- scratch ----------------
__device__ float g_Kproj[BB*LL*FF];
__device__ float g_LV[BB*LL*FF];
__device__ unsigned char g_mask[BB*LL];
__device__ float g_q[MROWS*FF];
__device__ float g_r[MROWS*FF];
__device__ float g_pre[MROWS*FF];

// ---------------- lane projection ----------------
template<bool LOGSIG>
__global__ __launch_bounds__(256) void lane_proj_kernel(
    const float* __restrict__ lanes, const float* __restrict__ W,
    const float* __restrict__ bias, float* __restrict__ out)
{
    __shared__ float Wsh[LFF][FF + 1];
    __shared__ float lsh[32][LFF];
    __shared__ float bsh[FF];
    int tid = threadIdx.x;
    int row0 = blockIdx.x * 32;

    #pragma unroll
    for (int i = 0; i < 32; i++) {
        int idx = tid + i * 256;
        int f = idx >> 6, j = idx & 63;
        Wsh[j][f] = W[idx];
    }
    if (tid < FF) bsh[tid] = bias[tid];
    #pragma unroll
    for (int i = 0; i < 2; i++) {
        int idx = tid + i * 256;
        int r = idx >> 4;
        int c = (idx & 15) * 4;
        *(float4*)&lsh[r][c] = *(const float4*)(lanes + (size_t)(row0 + r) * LFF + c);
    }
    __syncthreads();

    int f = tid & 127;
    for (int r = tid >> 7; r < 32; r += 2) {
        float acc = bsh[f];
        #pragma unroll
        for (int j = 0; j < LFF; j++) acc += lsh[r][j] * Wsh[j][f];
        if (LOGSIG) {
            acc = (acc >= 0.f) ? -__logf(1.f + __expf(-acc))
                               : acc - __logf(1.f + __expf(acc));
        }
        out[(size_t)(row0 + r) * FF + f] = acc;
    }
}

// ---------------- mask ----------------
__global__ void mask_kernel(const unsigned char* __restrict__ m)
{
    int tid = threadIdx.x;
    const unsigned int* w = (const unsigned int*)m;
    bool okI = true, okF = true;
    for (int j = tid; j < (HISTN * BB * LL) / 4; j += 256) {
        unsigned int x = w[j];
        if (x > 1u) okI = false;
        if (x != 0u && x != 0x3F800000u) okF = false;
    }
    okI = __syncthreads_and((int)okI) != 0;
    okF = __syncthreads_and((int)okF) != 0;
    int cls = okI ? 0 : (okF ? 1 : 2);

    for (int i = tid; i < BB * LL; i += 256) {
        unsigned int any = 0;
        #pragma unroll
        for (int h = 0; h < HISTN; h++) {
            int j = h * BB * LL + i;
            unsigned int v;
            if (cls == 0)      v = w[j];
            else if (cls == 1) v = (w[j] != 0u);
            else               v = m[j];
            any |= v;
        }
        g_mask[i] = any ? 1 : 0;
    }
}

// ---------------- 30720x128x128 GEMM (packed f32x2) ----------------
template<bool SUM_AB, bool EPI>
__global__ __launch_bounds__(256) void gemm128_kernel(
    const float* __restrict__ A1, const float* __restrict__ A2,
    const float* __restrict__ W,  const float* __restrict__ bias,
    float* __restrict__ C,
    const float* __restrict__ E1, const float* __restrict__ E2)
{
    __shared__ float Ash[64][36];
    __shared__ float Wsh[32][132];
    int tid = threadIdx.x;
    int tx = tid & 31, ty = tid >> 5;
    int m0 = blockIdx.x * 64;

    u64 acc2[8][2];
    #pragma unroll
    for (int i = 0; i < 8; i++) { acc2[i][0] = 0ull; acc2[i][1] = 0ull; }

    for (int k0 = 0; k0 < 128; k0 += 32) {
        #pragma unroll
        for (int i = 0; i < 2; i++) {
            int idx = tid + i * 256;
            int row = idx >> 3, c = (idx & 7) * 4;
            float4 a = *(const float4*)(A1 + (size_t)(m0 + row) * FF + k0 + c);
            if (SUM_AB) {
                float4 b = *(const float4*)(A2 + (size_t)(m0 + row) * FF + k0 + c);
                a.x += b.x; a.y += b.y; a.z += b.z; a.w += b.w;
            }
            *(float4*)&Ash[row][c] = a;
        }
        #pragma unroll
        for (int i = 0; i < 16; i++) {
            int idx = tid + i * 256;
            int n = idx >> 5, kk = idx & 31;
            Wsh[kk][n] = W[n * FF + k0 + kk];
        }
        __syncthreads();
        #pragma unroll
        for (int k = 0; k < 32; k++) {
            ulonglong2 b2 = *(ulonglong2*)&Wsh[k][tx * 4];
            #pragma unroll
            for (int i = 0; i < 8; i++) {
                float a = Ash[ty * 8 + i][k];
                u64 a2 = pk2(a, a);
                fma2(acc2[i][0], a2, b2.x);
                fma2(acc2[i][1], a2, b2.y);
            }
        }
        __syncthreads();
    }

    int n = tx * 4;
    float4 bb = *(const float4*)(bias + n);
    #pragma unroll
    for (int i = 0; i < 8; i++) {
        int m = m0 + ty * 8 + i;
        float2 lo = up2(acc2[i][0]), hi = up2(acc2[i][1]);
        float4 o;
        o.x = lo.x + bb.x; o.y = lo.y + bb.y;
        o.z = hi.x + bb.z; o.w = hi.y + bb.w;
        if (EPI) {
            float4 e1 = *(const float4*)(E1 + (size_t)m * FF + n);
            float4 e2 = *(const float4*)(E2 + (size_t)m * FF + n);
            o.x += e1.x - e2.x; o.y += e1.y - e2.y;
            o.z += e1.z - e2.z; o.w += e1.w - e2.w;
        }
        *(float4*)(C + (size_t)m * FF + n) = o;
    }
}

// ---------------- fused q+r GEMM (packed f32x2) ----------------
__global__ __launch_bounds__(256, 2) void gemm_qr_kernel(
    const float* __restrict__ A1, const float* __restrict__ A2,
    const float* __restrict__ Wq, const float* __restrict__ bq,
    const float* __restrict__ Wr, const float* __restrict__ br,
    float* __restrict__ Cq, float* __restrict__ Cr)
{
    __shared__ float Ash[64][36];
    __shared__ float W1[32][132];
    __shared__ float W2[32][132];
    int tid = threadIdx.x;
    int tx = tid & 31, ty = tid >> 5;
    int m0 = blockIdx.x * 64;

    u64 aq[8][2], ar[8][2];
    #pragma unroll
    for (int i = 0; i < 8; i++) {
        aq[i][0] = aq[i][1] = 0ull;
        ar[i][0] = ar[i][1] = 0ull;
    }

    for (int k0 = 0; k0 < 128; k0 += 32) {
        #pragma unroll
        for (int i = 0; i < 2; i++) {
            int idx = tid + i * 256;
            int row = idx >> 3, c = (idx & 7) * 4;
            float4 a = *(const float4*)(A1 + (size_t)(m0 + row) * FF + k0 + c);
            float4 b = *(const float4*)(A2 + (size_t)(m0 + row) * FF + k0 + c);
            a.x += b.x; a.y += b.y; a.z += b.z; a.w += b.w;
            *(float4*)&Ash[row][c] = a;
        }
        #pragma unroll
        for (int i = 0; i < 16; i++) {
            int idx = tid + i * 256;
            int n = idx >> 5, kk = idx & 31;
            W1[kk][n] = Wq[n * FF + k0 + kk];
            W2[kk][n] = Wr[n * FF + k0 + kk];
        }
        __syncthreads();
        #pragma unroll
        for (int k = 0; k < 32; k++) {
            ulonglong2 q2 = *(ulonglong2*)&W1[k][tx * 4];
            ulonglong2 r2 = *(ulonglong2*)&W2[k][tx * 4];
            #pragma unroll
            for (int i = 0; i < 8; i++) {
                float a = Ash[ty * 8 + i][k];
                u64 a2 = pk2(a, a);
                fma2(aq[i][0], a2, q2.x);
                fma2(aq[i][1], a2, q2.y);
                fma2(ar[i][0], a2, r2.x);
                fma2(ar[i][1], a2, r2.y);
            }
        }
        __syncthreads();
    }

    int n = tx * 4;
    float4 bq4 = *(const float4*)(bq + n);
    float4 br4 = *(const float4*)(br + n);
    #pragma unroll
    for (int i = 0; i < 8; i++) {
        int m = m0 + ty * 8 + i;
        float2 qlo = up2(aq[i][0]), qhi = up2(aq[i][1]);
        float2 rlo = up2(ar[i][0]), rhi = up2(ar[i][1]);
        float4 oq, orr;
        oq.x  = qlo.x + bq4.x; oq.y  = qlo.y + bq4.y;
        oq.z  = qhi.x + bq4.z; oq.w  = qhi.y + bq4.w;
        orr.x = rlo.x + br4.x; orr.y = rlo.y + br4.y;
        orr.z = rhi.x + br4.z; orr.w = rhi.y + br4.w;
        *(float4*)(Cq + (size_t)m * FF + n) = oq;
        *(float4*)(Cr + (size_t)m * FF + n) = orr;
    }
}

// ---------------- attention v8: tensor-core, hoisted fragments, t-split grid ----------------
// grid (BB*HH, TT/ATB). K/LV MMA B-fragments loaded ONCE per block from gmem into
// registers (t-invariant). smem: qsh + sc + pb + sinv + msk = 52.4 KB.
#define ATB 6
#define BOFF_Q   0
#define BOFF_SC  640
#define BOFF_PB  8960
#define BOFF_SI  13120
#define BOFF_M   13152
#define BSMEM_FLOATS 13408
#define BSMEM_BYTES  (BSMEM_FLOATS * 4)

__global__ __launch_bounds__(256) void attn8_kernel()
{
    extern __shared__ float smp[];
    float* qsh  = smp + BOFF_Q;    // [32][20] tf32
    float* sc   = smp + BOFF_SC;   // [32][260]
    float* pb   = smp + BOFF_PB;   // [8][520]
    float* sinv = smp + BOFF_SI;   // [32]
    float* msk  = smp + BOFF_M;    // [256]

    int tid = threadIdx.x;
    int b = blockIdx.x >> 3, h = blockIdx.x & 7;
    int t0 = blockIdx.y * ATB;
    int w = tid >> 5, lane = tid & 31;
    int qr = lane >> 2, qc = lane & 3;

    // ---- hoisted t-invariant fragments (direct gmem loads, tf32) ----
    unsigned Kb[4][4];     // stage-A B-fragments: warp w owns n in [w*32, w*32+32)
    #pragma unroll
    for (int ni = 0; ni < 4; ni++) {
        int n = w * 32 + ni * 8 + qr;
        const float* kp = g_Kproj + ((size_t)(b * LL + n)) * FF + h * DHH;
        Kb[ni][0] = tf32u(kp[qc]);
        Kb[ni][1] = tf32u(kp[qc + 4]);
        Kb[ni][2] = tf32u(kp[qc + 8]);
        Kb[ni][3] = tf32u(kp[qc + 12]);
    }
    unsigned LVb[4][2][2]; // stage-B B-fragments: warp w owns k in [w*32, w*32+32)
    #pragma unroll
    for (int ki = 0; ki < 4; ki++) {
        int kk = w * 32 + ki * 8;
        const float* lv0 = g_LV + ((size_t)(b * LL + kk + qc)) * FF + h * DHH;
        const float* lv1 = g_LV + ((size_t)(b * LL + kk + qc + 4)) * FF + h * DHH;
        #pragma unroll
        for (int ni = 0; ni < 2; ni++) {
            LVb[ki][ni][0] = tf32u(lv0[ni * 8 + qr]);
            LVb[ki][ni][1] = tf32u(lv1[ni * 8 + qr]);
        }
    }
    msk[tid] = g_mask[b * LL + tid] ? 1.f : 0.f;

    for (int t = t0; t < t0 + ATB; t++) {
        __syncthreads();
        if (tid < 128) {   // q tile load + tf32 convert
            int v = tid >> 2, c4 = (tid & 3) * 4;
            float4 qv = *(const float4*)(g_q + ((size_t)((t * BB + b) * VV + v)) * FF + h * DHH + c4);
            qsh[v * 20 + c4 + 0] = __uint_as_float(tf32u(qv.x));
            qsh[v * 20 + c4 + 1] = __uint_as_float(tf32u(qv.y));
            qsh[v * 20 + c4 + 2] = __uint_as_float(tf32u(qv.z));
            qsh[v * 20 + c4 + 3] = __uint_as_float(tf32u(qv.w));
        }
        __syncthreads();

        // ---- Stage A: scores[32,256] = q @ K^T ----
        {
            unsigned Aq[2][2][4];
            #pragma unroll
            for (int mi = 0; mi < 2; mi++)
                #pragma unroll
                for (int ki = 0; ki < 2; ki++) {
                    int r = mi * 16 + qr;
                    Aq[mi][ki][0] = __float_as_uint(qsh[r * 20 + ki * 8 + qc]);
                    Aq[mi][ki][1] = __float_as_uint(qsh[(r + 8) * 20 + ki * 8 + qc]);
                    Aq[mi][ki][2] = __float_as_uint(qsh[r * 20 + ki * 8 + qc + 4]);
                    Aq[mi][ki][3] = __float_as_uint(qsh[(r + 8) * 20 + ki * 8 + qc + 4]);
                }
            float Cs[2][4][4];
            #pragma unroll
            for (int mi = 0; mi < 2; mi++)
                #pragma unroll
                for (int ni = 0; ni < 4; ni++)
                    #pragma unroll
                    for (int j = 0; j < 4; j++) Cs[mi][ni][j] = 0.f;

            #pragma unroll
            for (int ni = 0; ni < 4; ni++)
                #pragma unroll
                for (int mi = 0; mi < 2; mi++) {
                    mma_tf32(Cs[mi][ni], Aq[mi][0], Kb[ni][0], Kb[ni][1]);
                    mma_tf32(Cs[mi][ni], Aq[mi][1], Kb[ni][2], Kb[ni][3]);
                }

            #pragma unroll
            for (int mi = 0; mi < 2; mi++)
                #pragma unroll
                for (int ni = 0; ni < 4; ni++) {
                    int v = mi * 16 + qr;
                    int n = w * 32 + ni * 8 + 2 * qc;
                    float m0 = msk[n], m1 = msk[n + 1];
                    float2 s01, s23;
                    s01.x = (m0 != 0.f) ? Cs[mi][ni][0] * 0.25f : -1e9f;
                    s01.y = (m1 != 0.f) ? Cs[mi][ni][1] * 0.25f : -1e9f;
                    s23.x = (m0 != 0.f) ? Cs[mi][ni][2] * 0.25f : -1e9f;
                    s23.y = (m1 != 0.f) ? Cs[mi][ni][3] * 0.25f : -1e9f;
                    *(float2*)&sc[v * 260 + n] = s01;
                    *(float2*)&sc[(v + 8) * 260 + n] = s23;
                }
        }
        __syncthreads();

        // ---- softmax over l ----
        #pragma unroll
        for (int rr = 0; rr < 4; rr++) {
            int rv = w + rr * 8;
            float4 a = *(float4*)&sc[rv * 260 + lane * 8];
            float4 c = *(float4*)&sc[rv * 260 + lane * 8 + 4];
            float mx = fmaxf(fmaxf(fmaxf(a.x, a.y), fmaxf(a.z, a.w)),
                             fmaxf(fmaxf(c.x, c.y), fmaxf(c.z, c.w)));
            #pragma unroll
            for (int o = 16; o > 0; o >>= 1)
                mx = fmaxf(mx, __shfl_xor_sync(0xffffffffu, mx, o));
            a.x = __expf(a.x - mx); a.y = __expf(a.y - mx);
            a.z = __expf(a.z - mx); a.w = __expf(a.w - mx);
            c.x = __expf(c.x - mx); c.y = __expf(c.y - mx);
            c.z = __expf(c.z - mx); c.w = __expf(c.w - mx);
            float sm = ((a.x + a.y) + (a.z + a.w)) + ((c.x + c.y) + (c.z + c.w));
            #pragma unroll
            for (int o = 16; o > 0; o >>= 1)
                sm += __shfl_xor_sync(0xffffffffu, sm, o);
            *(float4*)&sc[rv * 260 + lane * 8] = a;
            *(float4*)&sc[rv * 260 + lane * 8 + 4] = c;
            if (lane == 0) sinv[rv] = __fdividef(1.f, sm);
        }
        __syncthreads();

        // ---- Stage B: out[32,16] = p @ LV (k-split across warps) ----
        {
            float Co[2][2][4];
            #pragma unroll
            for (int mi = 0; mi < 2; mi++)
                #pragma unroll
                for (int ni = 0; ni < 2; ni++)
                    #pragma unroll
                    for (int j = 0; j < 4; j++) Co[mi][ni][j] = 0.f;

            #pragma unroll
            for (int ki = 0; ki < 4; ki++) {
                int kk = w * 32 + ki * 8;
                unsigned Ap[2][4];
                #pragma unroll
                for (int mi = 0; mi < 2; mi++) {
                    int r = mi * 16 + qr;
                    Ap[mi][0] = tf32u(sc[r * 260 + kk + qc]);
                    Ap[mi][1] = tf32u(sc[(r + 8) * 260 + kk + qc]);
                    Ap[mi][2] = tf32u(sc[r * 260 + kk + qc + 4]);
                    Ap[mi][3] = tf32u(sc[(r + 8) * 260 + kk + qc + 4]);
                }
                #pragma unroll
                for (int ni = 0; ni < 2; ni++)
                    #pragma unroll
                    for (int mi = 0; mi < 2; mi++)
                        mma_tf32(Co[mi][ni], Ap[mi], LVb[ki][ni][0], LVb[ki][ni][1]);
            }
            #pragma unroll
            for (int mi = 0; mi < 2; mi++)
                #pragma unroll
                for (int ni = 0; ni < 2; ni++) {
                    int v = mi * 16 + qr;
                    int d = ni * 8 + 2 * qc;
                    float2 p01, p23;
                    p01.x = Co[mi][ni][0]; p01.y = Co[mi][ni][1];
                    p23.x = Co[mi][ni][2]; p23.y = Co[mi][ni][3];
                    *(float2*)&pb[w * 520 + v * 16 + d] = p01;
                    *(float2*)&pb[w * 520 + (v + 8) * 16 + d] = p23;
                }
        }
        __syncthreads();

        // ---- cross-warp reduce + exp epilogue ----
        {
            int v = tid >> 3;
            int d = (tid & 7) * 2;
            float2 s = make_float2(0.f, 0.f);
            #pragma unroll
            for (int ww = 0; ww < 8; ww++) {
                float2 p = *(float2*)&pb[ww * 520 + tid * 2];
                s.x += p.x; s.y += p.y;
            }
            float si = sinv[v];
            float2 r2 = *(const float2*)(g_r + ((size_t)((t * BB + b) * VV + v)) * FF + h * DHH + d);
            float2 res;
            res.x = r2.x * __expf(s.x * si);
            res.y = r2.y * __expf(s.y * si);
            *(float2*)(g_pre + ((size_t)(t * BB + b)) * (VV * FF)
                       + h * (VV * DHH) + v * DHH + d) = res;
        }
    }
}

// ---------------- launch ----------------
extern "C" void kernel_launch(void* const* d_in, const int* in_sizes, int n_in,
                              void* d_out, int out_size)
{
    const float* vehicles    = (const float*)d_in[0];
    const float* initial_pos = (const float*)d_in[1];
    const float* lanes       = (const float*)d_in[2];
    const unsigned char* mask_lanes = (const unsigned char*)d_in[3];
    const float* Wk = (const float*)d_in[4];
    const float* bk = (const float*)d_in[5];
    const float* Wv = (const float*)d_in[6];
    const float* bv = (const float*)d_in[7];
    const float* Wq = (const float*)d_in[8];
    const float* bq = (const float*)d_in[9];
    const float* Wr = (const float*)d_in[10];
    const float* br = (const float*)d_in[11];
    const float* Wc = (const float*)d_in[12];
    const float* bc = (const float*)d_in[13];
    float* out = (float*)d_out;

    cudaFuncSetAttribute(attn8_kernel,
                         cudaFuncAttributeMaxDynamicSharedMemorySize, BSMEM_BYTES);
    cudaFuncSetAttribute(attn8_kernel,
                         cudaFuncAttributePreferredSharedMemoryCarveout,
                         cudaSharedmemCarveoutMaxShared);

    float *gK, *gLV, *gq, *gr, *gpre;
    cudaGetSymbolAddress((void**)&gK,   g_Kproj);
    cudaGetSymbolAddress((void**)&gLV,  g_LV);
    cudaGetSymbolAddress((void**)&gq,   g_q);
    cudaGetSymbolAddress((void**)&gr,   g_r);
    cudaGetSymbolAddress((void**)&gpre, g_pre);

    // 1) lane projections + mask
    lane_proj_kernel<false><<<BB * LL / 32, 256>>>(lanes, Wk, bk, gK);
    lane_proj_kernel<true ><<<BB * LL / 32, 256>>>(lanes, Wv, bv, gLV);
    mask_kernel<<<1, 256>>>(mask_lanes);

    // 2) fused q, r projections
    gemm_qr_kernel<<<MROWS / 64, 256>>>(vehicles, initial_pos, Wq, bq, Wr, br, gq, gr);

    // 3) attention (tensor cores, hoisted fragments, t-split)
    attn8_kernel<<<dim3(BB * HH, TT / ATB), 256, BSMEM_BYTES>>>();

    // 4) combine + residual
    gemm128_kernel<false, true><<<MROWS / 64, 256>>>(gpre, nullptr, Wc, bc, out, vehicles, initial_pos);
}

// round 14
// speedup vs baseline: 1.6567x; 1.0459x over previous
#include <cuda_runtime.h>
#include <cuda_fp16.h>
#include <math.h>

#define TT   30
#define BB   32
#define VV   32
#define FF   128
#define LL   256
#define LFF  64
#define HH   8
#define DHH  16
#define HISTN 10
#define MROWS (TT*BB*VV)   // 30720

typedef unsigned long long u64;

// ---- packed f32x2 helpers (GEMMs only) ----
__device__ __forceinline__ u64 pk2(float a, float b) {
    u64 r; asm("mov.b64 %0,{%1,%2};" : "=l"(r) : "f"(a), "f"(b)); return r;
}
__device__ __forceinline__ float2 up2(u64 v) {
    float2 f; asm("mov.b64 {%0,%1},%2;" : "=f"(f.x), "=f"(f.y) : "l"(v)); return f;
}
__device__ __forceinline__ void fma2(u64& d, u64 a, u64 b) {
    asm("fma.rn.f32x2 %0,%1,%2,%0;" : "+l"(d) : "l"(a), "l"(b));
}

// ---- mma helpers ----
__device__ __forceinline__ unsigned tf32u(float x) {
    unsigned u; asm("cvt.rna.tf32.f32 %0,%1;" : "=r"(u) : "f"(x)); return u;
}
__device__ __forceinline__ void mma_tf32(float* c, const unsigned* a, unsigned b0, unsigned b1) {
    asm volatile("mma.sync.aligned.m16n8k8.row.col.f32.tf32.tf32.f32 "
        "{%0,%1,%2,%3},{%4,%5,%6,%7},{%8,%9},{%0,%1,%2,%3};"
        : "+f"(c[0]), "+f"(c[1]), "+f"(c[2]), "+f"(c[3])
        : "r"(a[0]), "r"(a[1]), "r"(a[2]), "r"(a[3]), "r"(b0), "r"(b1));
}
__device__ __forceinline__ void mma_f16(float* c, const unsigned* a, unsigned b0, unsigned b1) {
    asm volatile("mma.sync.aligned.m16n8k16.row.col.f32.f16.f16.f32 "
        "{%0,%1,%2,%3},{%4,%5,%6,%7},{%8,%9},{%0,%1,%2,%3};"
        : "+f"(c[0]), "+f"(c[1]), "+f"(c[2]), "+f"(c[3])
        : "r"(a[0]), "r"(a[1]), "r"(a[2]), "r"(a[3]), "r"(b0), "r"(b1));
}
__device__ __forceinline__ unsigned h2ex2(unsigned h) {
    unsigned r; asm("ex2.approx.f16x2 %0,%1;" : "=r"(r) : "r"(h)); return r;
}
__device__ __forceinline__ unsigned packh2(float a, float b) {
    __half2 h = __floats2half2_rn(a, b); return *(unsigned*)&h;
}

// ---------------- scratch ----------------
__device__ float g_Kproj[BB*LL*FF];
__device__ float g_LV[BB*LL*FF];
__device__ unsigned char g_mask[BB*LL];
__device__ float g_q[MROWS*FF];
__device__ float g_r[MROWS*FF];
__device__ float g_pre[MROWS*FF];

// ---------------- lane projection ----------------
template<bool LOGSIG>
__global__ __launch_bounds__(256) void lane_proj_kernel(
    const float* __restrict__ lanes, const float* __restrict__ W,
    const float* __restrict__ bias, float* __restrict__ out)
{
    __shared__ float Wsh[LFF][FF + 1];
    __shared__ float lsh[32][LFF];
    __shared__ float bsh[FF];
    int tid = threadIdx.x;
    int row0 = blockIdx.x * 32;

    #pragma unroll
    for (int i = 0; i < 32; i++) {
        int idx = tid + i * 256;
        int f = idx >> 6, j = idx & 63;
        Wsh[j][f] = W[idx];
    }
    if (tid < FF) bsh[tid] = bias[tid];
    #pragma unroll
    for (int i = 0; i < 2; i++) {
        int idx = tid + i * 256;
        int r = idx >> 4;
        int c = (idx & 15) * 4;
        *(float4*)&lsh[r][c] = *(const float4*)(lanes + (size_t)(row0 + r) * LFF + c);
    }
    __syncthreads();

    int f = tid & 127;
    for (int r = tid >> 7; r < 32; r += 2) {
        float acc = bsh[f];
        #pragma unroll
        for (int j = 0; j < LFF; j++) acc += lsh[r][j] * Wsh[j][f];
        if (LOGSIG) {
            acc = (acc >= 0.f) ? -__logf(1.f + __expf(-acc))
                               : acc - __logf(1.f + __expf(acc));
        }
        out[(size_t)(row0 + r) * FF + f] = acc;
    }
}

// ---------------- mask ----------------
__global__ void mask_kernel(const unsigned char* __restrict__ m)
{
    int tid = threadIdx.x;
    const unsigned int* w = (const unsigned int*)m;
    bool okI = true, okF = true;
    for (int j = tid; j < (HISTN * BB * LL) / 4; j += 256) {
        unsigned int x = w[j];
        if (x > 1u) okI = false;
        if (x != 0u && x != 0x3F800000u) okF = false;
    }
    okI = __syncthreads_and((int)okI) != 0;
    okF = __syncthreads_and((int)okF) != 0;
    int cls = okI ? 0 : (okF ? 1 : 2);

    for (int i = tid; i < BB * LL; i += 256) {
        unsigned int any = 0;
        #pragma unroll
        for (int h = 0; h < HISTN; h++) {
            int j = h * BB * LL + i;
            unsigned int v;
            if (cls == 0)      v = w[j];
            else if (cls == 1) v = (w[j] != 0u);
            else               v = m[j];
            any |= v;
        }
        g_mask[i] = any ? 1 : 0;
    }
}

// ---------------- 30720x128x128 GEMM (packed f32x2) ----------------
template<bool SUM_AB, bool EPI>
__global__ __launch_bounds__(256) void gemm128_kernel(
    const float* __restrict__ A1, const float* __restrict__ A2,
    const float* __restrict__ W,  const float* __restrict__ bias,
    float* __restrict__ C,
    const float* __restrict__ E1, const float* __restrict__ E2)
{
    __shared__ float Ash[64][36];
    __shared__ float Wsh[32][132];
    int tid = threadIdx.x;
    int tx = tid & 31, ty = tid >> 5;
    int m0 = blockIdx.x * 64;

    u64 acc2[8][2];
    #pragma unroll
    for (int i = 0; i < 8; i++) { acc2[i][0] = 0ull; acc2[i][1] = 0ull; }

    for (int k0 = 0; k0 < 128; k0 += 32) {
        #pragma unroll
        for (int i = 0; i < 2; i++) {
            int idx = tid + i * 256;
            int row = idx >> 3, c = (idx & 7) * 4;
            float4 a = *(const float4*)(A1 + (size_t)(m0 + row) * FF + k0 + c);
            if (SUM_AB) {
                float4 b = *(const float4*)(A2 + (size_t)(m0 + row) * FF + k0 + c);
                a.x += b.x; a.y += b.y; a.z += b.z; a.w += b.w;
            }
            *(float4*)&Ash[row][c] = a;
        }
        #pragma unroll
        for (int i = 0; i < 16; i++) {
            int idx = tid + i * 256;
            int n = idx >> 5, kk = idx & 31;
            Wsh[kk][n] = W[n * FF + k0 + kk];
        }
        __syncthreads();
        #pragma unroll
        for (int k = 0; k < 32; k++) {
            ulonglong2 b2 = *(ulonglong2*)&Wsh[k][tx * 4];
            #pragma unroll
            for (int i = 0; i < 8; i++) {
                float a = Ash[ty * 8 + i][k];
                u64 a2 = pk2(a, a);
                fma2(acc2[i][0], a2, b2.x);
                fma2(acc2[i][1], a2, b2.y);
            }
        }
        __syncthreads();
    }

    int n = tx * 4;
    float4 bb = *(const float4*)(bias + n);
    #pragma unroll
    for (int i = 0; i < 8; i++) {
        int m = m0 + ty * 8 + i;
        float2 lo = up2(acc2[i][0]), hi = up2(acc2[i][1]);
        float4 o;
        o.x = lo.x + bb.x; o.y = lo.y + bb.y;
        o.z = hi.x + bb.z; o.w = hi.y + bb.w;
        if (EPI) {
            float4 e1 = *(const float4*)(E1 + (size_t)m * FF + n);
            float4 e2 = *(const float4*)(E2 + (size_t)m * FF + n);
            o.x += e1.x - e2.x; o.y += e1.y - e2.y;
            o.z += e1.z - e2.z; o.w += e1.w - e2.w;
        }
        *(float4*)(C + (size_t)m * FF + n) = o;
    }
}

// ---------------- fused q+r GEMM (packed f32x2) ----------------
__global__ __launch_bounds__(256, 2) void gemm_qr_kernel(
    const float* __restrict__ A1, const float* __restrict__ A2,
    const float* __restrict__ Wq, const float* __restrict__ bq,
    const float* __restrict__ Wr, const float* __restrict__ br,
    float* __restrict__ Cq, float* __restrict__ Cr)
{
    __shared__ float Ash[64][36];
    __shared__ float W1[32][132];
    __shared__ float W2[32][132];
    int tid = threadIdx.x;
    int tx = tid & 31, ty = tid >> 5;
    int m0 = blockIdx.x * 64;

    u64 aq[8][2], ar[8][2];
    #pragma unroll
    for (int i = 0; i < 8; i++) {
        aq[i][0] = aq[i][1] = 0ull;
        ar[i][0] = ar[i][1] = 0ull;
    }

    for (int k0 = 0; k0 < 128; k0 += 32) {
        #pragma unroll
        for (int i = 0; i < 2; i++) {
            int idx = tid + i * 256;
            int row = idx >> 3, c = (idx & 7) * 4;
            float4 a = *(const float4*)(A1 + (size_t)(m0 + row) * FF + k0 + c);
            float4 b = *(const float4*)(A2 + (size_t)(m0 + row) * FF + k0 + c);
            a.x += b.x; a.y += b.y; a.z += b.z; a.w += b.w;
            *(float4*)&Ash[row][c] = a;
        }
        #pragma unroll
        for (int i = 0; i < 16; i++) {
            int idx = tid + i * 256;
            int n = idx >> 5, kk = idx & 31;
            W1[kk][n] = Wq[n * FF + k0 + kk];
            W2[kk][n] = Wr[n * FF + k0 + kk];
        }
        __syncthreads();
        #pragma unroll
        for (int k = 0; k < 32; k++) {
            ulonglong2 q2 = *(ulonglong2*)&W1[k][tx * 4];
            ulonglong2 r2 = *(ulonglong2*)&W2[k][tx * 4];
            #pragma unroll
            for (int i = 0; i < 8; i++) {
                float a = Ash[ty * 8 + i][k];
                u64 a2 = pk2(a, a);
                fma2(aq[i][0], a2, q2.x);
                fma2(aq[i][1], a2, q2.y);
                fma2(ar[i][0], a2, r2.x);
                fma2(ar[i][1], a2, r2.y);
            }
        }
        __syncthreads();
    }

    int n = tx * 4;
    float4 bq4 = *(const float4*)(bq + n);
    float4 br4 = *(const float4*)(br + n);
    #pragma unroll
    for (int i = 0; i < 8; i++) {
        int m = m0 + ty * 8 + i;
        float2 qlo = up2(aq[i][0]), qhi = up2(aq[i][1]);
        float2 rlo = up2(ar[i][0]), rhi = up2(ar[i][1]);
        float4 oq, orr;
        oq.x  = qlo.x + bq4.x; oq.y  = qlo.y + bq4.y;
        oq.z  = qhi.x + bq4.z; oq.w  = qhi.y + bq4.w;
        orr.x = rlo.x + br4.x; orr.y = rlo.y + br4.y;
        orr.z = rhi.x + br4.z; orr.w = rhi.y + br4.w;
        *(float4*)(Cq + (size_t)m * FF + n) = oq;
        *(float4*)(Cr + (size_t)m * FF + n) = orr;
    }
}

// ---------------- attention v9: ex2.f16x2 softmax + fp16 stage B ----------------
// Score scale folds 0.25*log2(e) so softmax uses raw ex2. p kept in fp16 (sch),
// stage B uses m16n8k16.f16 MMAs. Everything else identical to attn8.
#define ATB 6
#define BOFF_Q   0
#define BOFF_SC  640
#define BOFF_PB  8960
#define BOFF_SI  13120
#define BOFF_M   13152
#define BOFF_PH  13408                       // half [32][264] = 4224 floats
#define BSMEM_FLOATS (13408 + 4224)
#define BSMEM_BYTES  (BSMEM_FLOATS * 4)
#define SCALE_LOG2E 0.3606737602222409f      // 0.25 * log2(e)

__global__ __launch_bounds__(256) void attn9_kernel()
{
    extern __shared__ float smp[];
    float* qsh  = smp + BOFF_Q;    // [32][20] tf32
    float* sc   = smp + BOFF_SC;   // [32][260] f32 scores
    float* pb   = smp + BOFF_PB;   // [8][520]
    float* sinv = smp + BOFF_SI;   // [32]
    float* msk  = smp + BOFF_M;    // [256]
    unsigned* sch = (unsigned*)(smp + BOFF_PH);  // p as half, row stride 132 words

    int tid = threadIdx.x;
    int b = blockIdx.x >> 3, h = blockIdx.x & 7;
    int t0 = blockIdx.y * ATB;
    int w = tid >> 5, lane = tid & 31;
    int qr = lane >> 2, qc = lane & 3;

    // ---- hoisted t-invariant fragments ----
    unsigned Kb[4][4];     // stage-A B-fragments (tf32): warp w owns n in [w*32, w*32+32)
    #pragma unroll
    for (int ni = 0; ni < 4; ni++) {
        int n = w * 32 + ni * 8 + qr;
        const float* kp = g_Kproj + ((size_t)(b * LL + n)) * FF + h * DHH;
        Kb[ni][0] = tf32u(kp[qc]);
        Kb[ni][1] = tf32u(kp[qc + 4]);
        Kb[ni][2] = tf32u(kp[qc + 8]);
        Kb[ni][3] = tf32u(kp[qc + 12]);
    }
    unsigned LVh[2][2][2]; // stage-B B-fragments (f16): warp w owns k in [w*32, w*32+32)
    #pragma unroll
    for (int ki = 0; ki < 2; ki++) {
        int kk = w * 32 + ki * 16;
        #pragma unroll
        for (int ni = 0; ni < 2; ni++) {
            int d = ni * 8 + qr;
            const float* base = g_LV + ((size_t)(b * LL)) * FF + h * DHH + d;
            float x0 = base[(size_t)(kk + 2 * qc) * FF];
            float x1 = base[(size_t)(kk + 2 * qc + 1) * FF];
            float x2 = base[(size_t)(kk + 2 * qc + 8) * FF];
            float x3 = base[(size_t)(kk + 2 * qc + 9) * FF];
            LVh[ki][ni][0] = packh2(x0, x1);
            LVh[ki][ni][1] = packh2(x2, x3);
        }
    }
    msk[tid] = g_mask[b * LL + tid] ? 1.f : 0.f;

    for (int t = t0; t < t0 + ATB; t++) {
        __syncthreads();
        if (tid < 128) {   // q tile load + tf32 convert
            int v = tid >> 2, c4 = (tid & 3) * 4;
            float4 qv = *(const float4*)(g_q + ((size_t)((t * BB + b) * VV + v)) * FF + h * DHH + c4);
            qsh[v * 20 + c4 + 0] = __uint_as_float(tf32u(qv.x));
            qsh[v * 20 + c4 + 1] = __uint_as_float(tf32u(qv.y));
            qsh[v * 20 + c4 + 2] = __uint_as_float(tf32u(qv.z));
            qsh[v * 20 + c4 + 3] = __uint_as_float(tf32u(qv.w));
        }
        __syncthreads();

        // ---- Stage A: scores[32,256] = q @ K^T (tf32), scaled by 0.25*log2e ----
        {
            unsigned Aq[2][2][4];
            #pragma unroll
            for (int mi = 0; mi < 2; mi++)
                #pragma unroll
                for (int ki = 0; ki < 2; ki++) {
                    int r = mi * 16 + qr;
                    Aq[mi][ki][0] = __float_as_uint(qsh[r * 20 + ki * 8 + qc]);
                    Aq[mi][ki][1] = __float_as_uint(qsh[(r + 8) * 20 + ki * 8 + qc]);
                    Aq[mi][ki][2] = __float_as_uint(qsh[r * 20 + ki * 8 + qc + 4]);
                    Aq[mi][ki][3] = __float_as_uint(qsh[(r + 8) * 20 + ki * 8 + qc + 4]);
                }
            float Cs[2][4][4];
            #pragma unroll
            for (int mi = 0; mi < 2; mi++)
                #pragma unroll
                for (int ni = 0; ni < 4; ni++)
                    #pragma unroll
                    for (int j = 0; j < 4; j++) Cs[mi][ni][j] = 0.f;

            #pragma unroll
            for (int ni = 0; ni < 4; ni++)
                #pragma unroll
                for (int mi = 0; mi < 2; mi++) {
                    mma_tf32(Cs[mi][ni], Aq[mi][0], Kb[ni][0], Kb[ni][1]);
                    mma_tf32(Cs[mi][ni], Aq[mi][1], Kb[ni][2], Kb[ni][3]);
                }

            #pragma unroll
            for (int mi = 0; mi < 2; mi++)
                #pragma unroll
                for (int ni = 0; ni < 4; ni++) {
                    int v = mi * 16 + qr;
                    int n = w * 32 + ni * 8 + 2 * qc;
                    float m0 = msk[n], m1 = msk[n + 1];
                    float2 s01, s23;
                    s01.x = (m0 != 0.f) ? Cs[mi][ni][0] * SCALE_LOG2E : -1e9f;
                    s01.y = (m1 != 0.f) ? Cs[mi][ni][1] * SCALE_LOG2E : -1e9f;
                    s23.x = (m0 != 0.f) ? Cs[mi][ni][2] * SCALE_LOG2E : -1e9f;
                    s23.y = (m1 != 0.f) ? Cs[mi][ni][3] * SCALE_LOG2E : -1e9f;
                    *(float2*)&sc[v * 260 + n] = s01;
                    *(float2*)&sc[(v + 8) * 260 + n] = s23;
                }
        }
        __syncthreads();

        // ---- softmax (base-2): max-reduce f32, ex2.f16x2, sum, store p as half ----
        #pragma unroll
        for (int rr = 0; rr < 4; rr++) {
            int rv = w + rr * 8;
            float4 a = *(float4*)&sc[rv * 260 + lane * 8];
            float4 c = *(float4*)&sc[rv * 260 + lane * 8 + 4];
            float mx = fmaxf(fmaxf(fmaxf(a.x, a.y), fmaxf(a.z, a.w)),
                             fmaxf(fmaxf(c.x, c.y), fmaxf(c.z, c.w)));
            #pragma unroll
            for (int o = 16; o > 0; o >>= 1)
                mx = fmaxf(mx, __shfl_xor_sync(0xffffffffu, mx, o));
            unsigned h0 = h2ex2(packh2(a.x - mx, a.y - mx));
            unsigned h1 = h2ex2(packh2(a.z - mx, a.w - mx));
            unsigned h2 = h2ex2(packh2(c.x - mx, c.y - mx));
            unsigned h3 = h2ex2(packh2(c.z - mx, c.w - mx));
            __half2 hs = __hadd2(__hadd2(*(__half2*)&h0, *(__half2*)&h1),
                                 __hadd2(*(__half2*)&h2, *(__half2*)&h3));
            float sm = __low2float(hs) + __high2float(hs);
            #pragma unroll
            for (int o = 16; o > 0; o >>= 1)
                sm += __shfl_xor_sync(0xffffffffu, sm, o);
            uint4 pk4; pk4.x = h0; pk4.y = h1; pk4.z = h2; pk4.w = h3;
            *(uint4*)&sch[rv * 132 + lane * 4] = pk4;
            if (lane == 0) sinv[rv] = __fdividef(1.f, sm);
        }
        __syncthreads();

        // ---- Stage B: out[32,16] = p @ LV (f16 MMA, k-split across warps) ----
        {
            float Co[2][2][4];
            #pragma unroll
            for (int mi = 0; mi < 2; mi++)
                #pragma unroll
                for (int ni = 0; ni < 2; ni++)
                    #pragma unroll
                    for (int j = 0; j < 4; j++) Co[mi][ni][j] = 0.f;

            #pragma unroll
            for (int ki = 0; ki < 2; ki++) {
                int kword = w * 16 + ki * 8;   // b32 word offset within row
                unsigned Ap[2][4];
                #pragma unroll
                for (int mi = 0; mi < 2; mi++) {
                    int r = mi * 16 + qr;
                    Ap[mi][0] = sch[r * 132 + kword + qc];
                    Ap[mi][1] = sch[(r + 8) * 132 + kword + qc];
                    Ap[mi][2] = sch[r * 132 + kword + qc + 4];
                    Ap[mi][3] = sch[(r + 8) * 132 + kword + qc + 4];
                }
                #pragma unroll
                for (int ni = 0; ni < 2; ni++)
                    #pragma unroll
                    for (int mi = 0; mi < 2; mi++)
                        mma_f16(Co[mi][ni], Ap[mi], LVh[ki][ni][0], LVh[ki][ni][1]);
            }
            #pragma unroll
            for (int mi = 0; mi < 2; mi++)
                #pragma unroll
                for (int ni = 0; ni < 2; ni++) {
                    int v = mi * 16 + qr;
                    int d = ni * 8 + 2 * qc;
                    float2 p01, p23;
                    p01.x = Co[mi][ni][0]; p01.y = Co[mi][ni][1];
                    p23.x = Co[mi][ni][2]; p23.y = Co[mi][ni][3];
                    *(float2*)&pb[w * 520 + v * 16 + d] = p01;
                    *(float2*)&pb[w * 520 + (v + 8) * 16 + d] = p23;
                }
        }
        __syncthreads();

        // ---- cross-warp reduce + exp epilogue ----
        {
            int v = tid >> 3;
            int d = (tid & 7) * 2;
            float2 s = make_float2(0.f, 0.f);
            #pragma unroll
            for (int ww = 0; ww < 8; ww++) {
                float2 p = *(float2*)&pb[ww * 520 + tid * 2];
                s.x += p.x; s.y += p.y;
            }
            float si = sinv[v];
            float2 r2 = *(const float2*)(g_r + ((size_t)((t * BB + b) * VV + v)) * FF + h * DHH + d);
            float2 res;
            res.x = r2.x * __expf(s.x * si);
            res.y = r2.y * __expf(s.y * si);
            *(float2*)(g_pre + ((size_t)(t * BB + b)) * (VV * FF)
                       + h * (VV * DHH) + v * DHH + d) = res;
        }
    }
}

// ---------------- launch ----------------
extern "C" void kernel_launch(void* const* d_in, const int* in_sizes, int n_in,
                              void* d_out, int out_size)
{
    const float* vehicles    = (const float*)d_in[0];
    const float* initial_pos = (const float*)d_in[1];
    const float* lanes       = (const float*)d_in[2];
    const unsigned char* mask_lanes = (const unsigned char*)d_in[3];
    const float* Wk = (const float*)d_in[4];
    const float* bk = (const float*)d_in[5];
    const float* Wv = (const float*)d_in[6];
    const float* bv = (const float*)d_in[7];
    const float* Wq = (const float*)d_in[8];
    const float* bq = (const float*)d_in[9];
    const float* Wr = (const float*)d_in[10];
    const float* br = (const float*)d_in[11];
    const float* Wc = (const float*)d_in[12];
    const float* bc = (const float*)d_in[13];
    float* out = (float*)d_out;

    cudaFuncSetAttribute(attn9_kernel,
                         cudaFuncAttributeMaxDynamicSharedMemorySize, BSMEM_BYTES);
    cudaFuncSetAttribute(attn9_kernel,
                         cudaFuncAttributePreferredSharedMemoryCarveout,
                         cudaSharedmemCarveoutMaxShared);

    float *gK, *gLV, *gq, *gr, *gpre;
    cudaGetSymbolAddress((void**)&gK,   g_Kproj);
    cudaGetSymbolAddress((void**)&gLV,  g_LV);
    cudaGetSymbolAddress((void**)&gq,   g_q);
    cudaGetSymbolAddress((void**)&gr,   g_r);
    cudaGetSymbolAddress((void**)&gpre, g_pre);

    // 1) lane projections + mask
    lane_proj_kernel<false><<<BB * LL / 32, 256>>>(lanes, Wk, bk, gK);
    lane_proj_kernel<true ><<<BB * LL / 32, 256>>>(lanes, Wv, bv, gLV);
    mask_kernel<<<1, 256>>>(mask_lanes);

    // 2) fused q, r projections
    gemm_qr_kernel<<<MROWS / 64, 256>>>(vehicles, initial_pos, Wq, bq, Wr, br, gq, gr);

    // 3) attention (tensor cores, f16x2 exp, fp16 PV)
    attn9_kernel<<<dim3(BB * HH, TT / ATB), 256, BSMEM_BYTES>>>();

    // 4) combine + residual
    gemm128_kernel<false, true><<<MROWS / 64, 256>>>(gpre, nullptr, Wc, bc, out, vehicles, initial_pos);
}

// round 15
// speedup vs baseline: 1.9488x; 1.1763x over previous
#include <cuda_runtime.h>
#include <cuda_fp16.h>
#include <math.h>

#define TT   30
#define BB   32
#define VV   32
#define FF   128
#define LL   256
#define LFF  64
#define HH   8
#define DHH  16
#define HISTN 10
#define MROWS (TT*BB*VV)   // 30720

// ---- mma helpers ----
__device__ __forceinline__ unsigned tf32u(float x) {
    unsigned u; asm("cvt.rna.tf32.f32 %0,%1;" : "=r"(u) : "f"(x)); return u;
}
__device__ __forceinline__ void mma_tf32(float* c, const unsigned* a, unsigned b0, unsigned b1) {
    asm volatile("mma.sync.aligned.m16n8k8.row.col.f32.tf32.tf32.f32 "
        "{%0,%1,%2,%3},{%4,%5,%6,%7},{%8,%9},{%0,%1,%2,%3};"
        : "+f"(c[0]), "+f"(c[1]), "+f"(c[2]), "+f"(c[3])
        : "r"(a[0]), "r"(a[1]), "r"(a[2]), "r"(a[3]), "r"(b0), "r"(b1));
}
__device__ __forceinline__ void mma_f16(float* c, const unsigned* a, unsigned b0, unsigned b1) {
    asm volatile("mma.sync.aligned.m16n8k16.row.col.f32.f16.f16.f32 "
        "{%0,%1,%2,%3},{%4,%5,%6,%7},{%8,%9},{%0,%1,%2,%3};"
        : "+f"(c[0]), "+f"(c[1]), "+f"(c[2]), "+f"(c[3])
        : "r"(a[0]), "r"(a[1]), "r"(a[2]), "r"(a[3]), "r"(b0), "r"(b1));
}
__device__ __forceinline__ unsigned h2ex2(unsigned h) {
    unsigned r; asm("ex2.approx.f16x2 %0,%1;" : "=r"(r) : "r"(h)); return r;
}
__device__ __forceinline__ unsigned packh2(float a, float b) {
    __half2 h = __floats2half2_rn(a, b); return *(unsigned*)&h;
}

// ---------------- scratch ----------------
__device__ float g_Kproj[BB*LL*FF];
__device__ float g_LV[BB*LL*FF];
__device__ unsigned char g_mask[BB*LL];
__device__ float g_q[MROWS*FF];
__device__ float g_r[MROWS*FF];
__device__ float g_pre[MROWS*FF];

// ---------------- lane projection ----------------
template<bool LOGSIG>
__global__ __launch_bounds__(256) void lane_proj_kernel(
    const float* __restrict__ lanes, const float* __restrict__ W,
    const float* __restrict__ bias, float* __restrict__ out)
{
    __shared__ float Wsh[LFF][FF + 1];
    __shared__ float lsh[32][LFF];
    __shared__ float bsh[FF];
    int tid = threadIdx.x;
    int row0 = blockIdx.x * 32;

    #pragma unroll
    for (int i = 0; i < 32; i++) {
        int idx = tid + i * 256;
        int f = idx >> 6, j = idx & 63;
        Wsh[j][f] = W[idx];
    }
    if (tid < FF) bsh[tid] = bias[tid];
    #pragma unroll
    for (int i = 0; i < 2; i++) {
        int idx = tid + i * 256;
        int r = idx >> 4;
        int c = (idx & 15) * 4;
        *(float4*)&lsh[r][c] = *(const float4*)(lanes + (size_t)(row0 + r) * LFF + c);
    }
    __syncthreads();

    int f = tid & 127;
    for (int r = tid >> 7; r < 32; r += 2) {
        float acc = bsh[f];
        #pragma unroll
        for (int j = 0; j < LFF; j++) acc += lsh[r][j] * Wsh[j][f];
        if (LOGSIG) {
            acc = (acc >= 0.f) ? -__logf(1.f + __expf(-acc))
                               : acc - __logf(1.f + __expf(acc));
        }
        out[(size_t)(row0 + r) * FF + f] = acc;
    }
}

// ---------------- mask ----------------
__global__ void mask_kernel(const unsigned char* __restrict__ m)
{
    int tid = threadIdx.x;
    const unsigned int* w = (const unsigned int*)m;
    bool okI = true, okF = true;
    for (int j = tid; j < (HISTN * BB * LL) / 4; j += 256) {
        unsigned int x = w[j];
        if (x > 1u) okI = false;
        if (x != 0u && x != 0x3F800000u) okF = false;
    }
    okI = __syncthreads_and((int)okI) != 0;
    okF = __syncthreads_and((int)okF) != 0;
    int cls = okI ? 0 : (okF ? 1 : 2);

    for (int i = tid; i < BB * LL; i += 256) {
        unsigned int any = 0;
        #pragma unroll
        for (int h = 0; h < HISTN; h++) {
            int j = h * BB * LL + i;
            unsigned int v;
            if (cls == 0)      v = w[j];
            else if (cls == 1) v = (w[j] != 0u);
            else               v = m[j];
            any |= v;
        }
        g_mask[i] = any ? 1 : 0;
    }
}

// ---------------- tensor-core fused q+r GEMM: Cq/Cr = (A1+A2) @ W^T + b ----------------
// Block: M=64, N=128. 8 warps 2x4 (warp tile 32x32). K chunks of 32 (tf32 in smem).
__global__ __launch_bounds__(256) void gemm_qr_tc(
    const float* __restrict__ A1, const float* __restrict__ A2,
    const float* __restrict__ Wq, const float* __restrict__ bq,
    const float* __restrict__ Wr, const float* __restrict__ br,
    float* __restrict__ Cq, float* __restrict__ Cr)
{
    __shared__ float Ash[64][36];
    __shared__ float Wqs[128][36];
    __shared__ float Wrs[128][36];

    int tid = threadIdx.x;
    int m0 = blockIdx.x * 64;
    int w = tid >> 5, lane = tid & 31;
    int qr = lane >> 2, qc = lane & 3;
    int wm = (w >> 2) * 32, wn = (w & 3) * 32;

    float accq[2][4][4], accr[2][4][4];
    #pragma unroll
    for (int mi = 0; mi < 2; mi++)
        #pragma unroll
        for (int ni = 0; ni < 4; ni++)
            #pragma unroll
            for (int j = 0; j < 4; j++) { accq[mi][ni][j] = 0.f; accr[mi][ni][j] = 0.f; }

    for (int k0 = 0; k0 < 128; k0 += 32) {
        #pragma unroll
        for (int i = 0; i < 2; i++) {          // A: 64x32
            int idx = tid + i * 256;
            int row = idx >> 3, c4 = (idx & 7) * 4;
            float4 a = *(const float4*)(A1 + (size_t)(m0 + row) * FF + k0 + c4);
            float4 b = *(const float4*)(A2 + (size_t)(m0 + row) * FF + k0 + c4);
            float4 o;
            o.x = __uint_as_float(tf32u(a.x + b.x));
            o.y = __uint_as_float(tf32u(a.y + b.y));
            o.z = __uint_as_float(tf32u(a.z + b.z));
            o.w = __uint_as_float(tf32u(a.w + b.w));
            *(float4*)&Ash[row][c4] = o;
        }
        #pragma unroll
        for (int i = 0; i < 4; i++) {          // Wq, Wr: 128x32 each
            int idx = tid + i * 256;
            int n = idx >> 3, c4 = (idx & 7) * 4;
            float4 a = *(const float4*)(Wq + (size_t)n * FF + k0 + c4);
            float4 o;
            o.x = __uint_as_float(tf32u(a.x)); o.y = __uint_as_float(tf32u(a.y));
            o.z = __uint_as_float(tf32u(a.z)); o.w = __uint_as_float(tf32u(a.w));
            *(float4*)&Wqs[n][c4] = o;
            float4 r = *(const float4*)(Wr + (size_t)n * FF + k0 + c4);
            float4 p;
            p.x = __uint_as_float(tf32u(r.x)); p.y = __uint_as_float(tf32u(r.y));
            p.z = __uint_as_float(tf32u(r.z)); p.w = __uint_as_float(tf32u(r.w));
            *(float4*)&Wrs[n][c4] = p;
        }
        __syncthreads();

        #pragma unroll
        for (int k8 = 0; k8 < 4; k8++) {
            int kk = k8 * 8;
            unsigned Af[2][4];
            #pragma unroll
            for (int mi = 0; mi < 2; mi++) {
                int r = wm + mi * 16 + qr;
                Af[mi][0] = __float_as_uint(Ash[r][kk + qc]);
                Af[mi][1] = __float_as_uint(Ash[r + 8][kk + qc]);
                Af[mi][2] = __float_as_uint(Ash[r][kk + qc + 4]);
                Af[mi][3] = __float_as_uint(Ash[r + 8][kk + qc + 4]);
            }
            #pragma unroll
            for (int ni = 0; ni < 4; ni++) {
                int n = wn + ni * 8 + qr;
                unsigned bq0 = __float_as_uint(Wqs[n][kk + qc]);
                unsigned bq1 = __float_as_uint(Wqs[n][kk + qc + 4]);
                unsigned br0 = __float_as_uint(Wrs[n][kk + qc]);
                unsigned br1 = __float_as_uint(Wrs[n][kk + qc + 4]);
                #pragma unroll
                for (int mi = 0; mi < 2; mi++) {
                    mma_tf32(accq[mi][ni], Af[mi], bq0, bq1);
                    mma_tf32(accr[mi][ni], Af[mi], br0, br1);
                }
            }
        }
        __syncthreads();
    }

    // epilogue: bias + store (rows wm+mi*16+qr, +8; cols wn+ni*8+2qc, +1)
    #pragma unroll
    for (int ni = 0; ni < 4; ni++) {
        int n = wn + ni * 8 + 2 * qc;
        float2 bq2 = *(const float2*)(bq + n);
        float2 br2 = *(const float2*)(br + n);
        #pragma unroll
        for (int mi = 0; mi < 2; mi++) {
            int r = m0 + wm + mi * 16 + qr;
            float2 o;
            o.x = accq[mi][ni][0] + bq2.x; o.y = accq[mi][ni][1] + bq2.y;
            *(float2*)(Cq + (size_t)r * FF + n) = o;
            o.x = accq[mi][ni][2] + bq2.x; o.y = accq[mi][ni][3] + bq2.y;
            *(float2*)(Cq + (size_t)(r + 8) * FF + n) = o;
            o.x = accr[mi][ni][0] + br2.x; o.y = accr[mi][ni][1] + br2.y;
            *(float2*)(Cr + (size_t)r * FF + n) = o;
            o.x = accr[mi][ni][2] + br2.x; o.y = accr[mi][ni][3] + br2.y;
            *(float2*)(Cr + (size_t)(r + 8) * FF + n) = o;
        }
    }
}

// ---------------- tensor-core combine GEMM: out = A @ W^T + b + E1 - E2 ----------------
__global__ __launch_bounds__(256) void gemm_c_tc(
    const float* __restrict__ A, const float* __restrict__ W,
    const float* __restrict__ bias, float* __restrict__ C,
    const float* __restrict__ E1, const float* __restrict__ E2)
{
    __shared__ float Ash[64][36];
    __shared__ float Ws[128][36];

    int tid = threadIdx.x;
    int m0 = blockIdx.x * 64;
    int w = tid >> 5, lane = tid & 31;
    int qr = lane >> 2, qc = lane & 3;
    int wm = (w >> 2) * 32, wn = (w & 3) * 32;

    float acc[2][4][4];
    #pragma unroll
    for (int mi = 0; mi < 2; mi++)
        #pragma unroll
        for (int ni = 0; ni < 4; ni++)
            #pragma unroll
            for (int j = 0; j < 4; j++) acc[mi][ni][j] = 0.f;

    for (int k0 = 0; k0 < 128; k0 += 32) {
        #pragma unroll
        for (int i = 0; i < 2; i++) {
            int idx = tid + i * 256;
            int row = idx >> 3, c4 = (idx & 7) * 4;
            float4 a = *(const float4*)(A + (size_t)(m0 + row) * FF + k0 + c4);
            float4 o;
            o.x = __uint_as_float(tf32u(a.x)); o.y = __uint_as_float(tf32u(a.y));
            o.z = __uint_as_float(tf32u(a.z)); o.w = __uint_as_float(tf32u(a.w));
            *(float4*)&Ash[row][c4] = o;
        }
        #pragma unroll
        for (int i = 0; i < 4; i++) {
            int idx = tid + i * 256;
            int n = idx >> 3, c4 = (idx & 7) * 4;
            float4 a = *(const float4*)(W + (size_t)n * FF + k0 + c4);
            float4 o;
            o.x = __uint_as_float(tf32u(a.x)); o.y = __uint_as_float(tf32u(a.y));
            o.z = __uint_as_float(tf32u(a.z)); o.w = __uint_as_float(tf32u(a.w));
            *(float4*)&Ws[n][c4] = o;
        }
        __syncthreads();

        #pragma unroll
        for (int k8 = 0; k8 < 4; k8++) {
            int kk = k8 * 8;
            unsigned Af[2][4];
            #pragma unroll
            for (int mi = 0; mi < 2; mi++) {
                int r = wm + mi * 16 + qr;
                Af[mi][0] = __float_as_uint(Ash[r][kk + qc]);
                Af[mi][1] = __float_as_uint(Ash[r + 8][kk + qc]);
                Af[mi][2] = __float_as_uint(Ash[r][kk + qc + 4]);
                Af[mi][3] = __float_as_uint(Ash[r + 8][kk + qc + 4]);
            }
            #pragma unroll
            for (int ni = 0; ni < 4; ni++) {
                int n = wn + ni * 8 + qr;
                unsigned b0 = __float_as_uint(Ws[n][kk + qc]);
                unsigned b1 = __float_as_uint(Ws[n][kk + qc + 4]);
                #pragma unroll
                for (int mi = 0; mi < 2; mi++)
                    mma_tf32(acc[mi][ni], Af[mi], b0, b1);
            }
        }
        __syncthreads();
    }

    #pragma unroll
    for (int ni = 0; ni < 4; ni++) {
        int n = wn + ni * 8 + 2 * qc;
        float2 b2 = *(const float2*)(bias + n);
        #pragma unroll
        for (int mi = 0; mi < 2; mi++) {
            int r = m0 + wm + mi * 16 + qr;
            float2 e1 = *(const float2*)(E1 + (size_t)r * FF + n);
            float2 e2 = *(const float2*)(E2 + (size_t)r * FF + n);
            float2 o;
            o.x = acc[mi][ni][0] + b2.x + e1.x - e2.x;
            o.y = acc[mi][ni][1] + b2.y + e1.y - e2.y;
            *(float2*)(C + (size_t)r * FF + n) = o;
            e1 = *(const float2*)(E1 + (size_t)(r + 8) * FF + n);
            e2 = *(const float2*)(E2 + (size_t)(r + 8) * FF + n);
            o.x = acc[mi][ni][2] + b2.x + e1.x - e2.x;
            o.y = acc[mi][ni][3] + b2.y + e1.y - e2.y;
            *(float2*)(C + (size_t)(r + 8) * FF + n) = o;
        }
    }
}

// ---------------- attention v9 (unchanged from round 14) ----------------
#define ATB 6
#define BOFF_Q   0
#define BOFF_SC  640
#define BOFF_PB  8960
#define BOFF_SI  13120
#define BOFF_M   13152
#define BOFF_PH  13408
#define BSMEM_FLOATS (13408 + 4224)
#define BSMEM_BYTES  (BSMEM_FLOATS * 4)
#define SCALE_LOG2E 0.3606737602222409f

__global__ __launch_bounds__(256) void attn9_kernel()
{
    extern __shared__ float smp[];
    float* qsh  = smp + BOFF_Q;
    float* sc   = smp + BOFF_SC;
    float* pb   = smp + BOFF_PB;
    float* sinv = smp + BOFF_SI;
    float* msk  = smp + BOFF_M;
    unsigned* sch = (unsigned*)(smp + BOFF_PH);

    int tid = threadIdx.x;
    int b = blockIdx.x >> 3, h = blockIdx.x & 7;
    int t0 = blockIdx.y * ATB;
    int w = tid >> 5, lane = tid & 31;
    int qr = lane >> 2, qc = lane & 3;

    unsigned Kb[4][4];
    #pragma unroll
    for (int ni = 0; ni < 4; ni++) {
        int n = w * 32 + ni * 8 + qr;
        const float* kp = g_Kproj + ((size_t)(b * LL + n)) * FF + h * DHH;
        Kb[ni][0] = tf32u(kp[qc]);
        Kb[ni][1] = tf32u(kp[qc + 4]);
        Kb[ni][2] = tf32u(kp[qc + 8]);
        Kb[ni][3] = tf32u(kp[qc + 12]);
    }
    unsigned LVh[2][2][2];
    #pragma unroll
    for (int ki = 0; ki < 2; ki++) {
        int kk = w * 32 + ki * 16;
        #pragma unroll
        for (int ni = 0; ni < 2; ni++) {
            int d = ni * 8 + qr;
            const float* base = g_LV + ((size_t)(b * LL)) * FF + h * DHH + d;
            float x0 = base[(size_t)(kk + 2 * qc) * FF];
            float x1 = base[(size_t)(kk + 2 * qc + 1) * FF];
            float x2 = base[(size_t)(kk + 2 * qc + 8) * FF];
            float x3 = base[(size_t)(kk + 2 * qc + 9) * FF];
            LVh[ki][ni][0] = packh2(x0, x1);
            LVh[ki][ni][1] = packh2(x2, x3);
        }
    }
    msk[tid] = g_mask[b * LL + tid] ? 1.f : 0.f;

    for (int t = t0; t < t0 + ATB; t++) {
        __syncthreads();
        if (tid < 128) {
            int v = tid >> 2, c4 = (tid & 3) * 4;
            float4 qv = *(const float4*)(g_q + ((size_t)((t * BB + b) * VV + v)) * FF + h * DHH + c4);
            qsh[v * 20 + c4 + 0] = __uint_as_float(tf32u(qv.x));
            qsh[v * 20 + c4 + 1] = __uint_as_float(tf32u(qv.y));
            qsh[v * 20 + c4 + 2] = __uint_as_float(tf32u(qv.z));
            qsh[v * 20 + c4 + 3] = __uint_as_float(tf32u(qv.w));
        }
        __syncthreads();

        {
            unsigned Aq[2][2][4];
            #pragma unroll
            for (int mi = 0; mi < 2; mi++)
                #pragma unroll
                for (int ki = 0; ki < 2; ki++) {
                    int r = mi * 16 + qr;
                    Aq[mi][ki][0] = __float_as_uint(qsh[r * 20 + ki * 8 + qc]);
                    Aq[mi][ki][1] = __float_as_uint(qsh[(r + 8) * 20 + ki * 8 + qc]);
                    Aq[mi][ki][2] = __float_as_uint(qsh[r * 20 + ki * 8 + qc + 4]);
                    Aq[mi][ki][3] = __float_as_uint(qsh[(r + 8) * 20 + ki * 8 + qc + 4]);
                }
            float Cs[2][4][4];
            #pragma unroll
            for (int mi = 0; mi < 2; mi++)
                #pragma unroll
                for (int ni = 0; ni < 4; ni++)
                    #pragma unroll
                    for (int j = 0; j < 4; j++) Cs[mi][ni][j] = 0.f;

            #pragma unroll
            for (int ni = 0; ni < 4; ni++)
                #pragma unroll
                for (int mi = 0; mi < 2; mi++) {
                    mma_tf32(Cs[mi][ni], Aq[mi][0], Kb[ni][0], Kb[ni][1]);
                    mma_tf32(Cs[mi][ni], Aq[mi][1], Kb[ni][2], Kb[ni][3]);
                }

            #pragma unroll
            for (int mi = 0; mi < 2; mi++)
                #pragma unroll
                for (int ni = 0; ni < 4; ni++) {
                    int v = mi * 16 + qr;
                    int n = w * 32 + ni * 8 + 2 * qc;
                    float m0 = msk[n], m1 = msk[n + 1];
                    float2 s01, s23;
                    s01.x = (m0 != 0.f) ? Cs[mi][ni][0] * SCALE_LOG2E : -1e9f;
                    s01.y = (m1 != 0.f) ? Cs[mi][ni][1] * SCALE_LOG2E : -1e9f;
                    s23.x = (m0 != 0.f) ? Cs[mi][ni][2] * SCALE_LOG2E : -1e9f;
                    s23.y = (m1 != 0.f) ? Cs[mi][ni][3] * SCALE_LOG2E : -1e9f;
                    *(float2*)&sc[v * 260 + n] = s01;
                    *(float2*)&sc[(v + 8) * 260 + n] = s23;
                }
        }
        __syncthreads();

        #pragma unroll
        for (int rr = 0; rr < 4; rr++) {
            int rv = w + rr * 8;
            float4 a = *(float4*)&sc[rv * 260 + lane * 8];
            float4 c = *(float4*)&sc[rv * 260 + lane * 8 + 4];
            float mx = fmaxf(fmaxf(fmaxf(a.x, a.y), fmaxf(a.z, a.w)),
                             fmaxf(fmaxf(c.x, c.y), fmaxf(c.z, c.w)));
            #pragma unroll
            for (int o = 16; o > 0; o >>= 1)
                mx = fmaxf(mx, __shfl_xor_sync(0xffffffffu, mx, o));
            unsigned h0 = h2ex2(packh2(a.x - mx, a.y - mx));
            unsigned h1 = h2ex2(packh2(a.z - mx, a.w - mx));
            unsigned h2 = h2ex2(packh2(c.x - mx, c.y - mx));
            unsigned h3 = h2ex2(packh2(c.z - mx, c.w - mx));
            __half2 hs = __hadd2(__hadd2(*(__half2*)&h0, *(__half2*)&h1),
                                 __hadd2(*(__half2*)&h2, *(__half2*)&h3));
            float sm = __low2float(hs) + __high2float(hs);
            #pragma unroll
            for (int o = 16; o > 0; o >>= 1)
                sm += __shfl_xor_sync(0xffffffffu, sm, o);
            uint4 pk4; pk4.x = h0; pk4.y = h1; pk4.z = h2; pk4.w = h3;
            *(uint4*)&sch[rv * 132 + lane * 4] = pk4;
            if (lane == 0) sinv[rv] = __fdividef(1.f, sm);
        }
        __syncthreads();

        {
            float Co[2][2][4];
            #pragma unroll
            for (int mi = 0; mi < 2; mi++)
                #pragma unroll
                for (int ni = 0; ni < 2; ni++)
                    #pragma unroll
                    for (int j = 0; j < 4; j++) Co[mi][ni][j] = 0.f;

            #pragma unroll
            for (int ki = 0; ki < 2; ki++) {
                int kword = w * 16 + ki * 8;
                unsigned Ap[2][4];
                #pragma unroll
                for (int mi = 0; mi < 2; mi++) {
                    int r = mi * 16 + qr;
                    Ap[mi][0] = sch[r * 132 + kword + qc];
                    Ap[mi][1] = sch[(r + 8) * 132 + kword + qc];
                    Ap[mi][2] = sch[r * 132 + kword + qc + 4];
                    Ap[mi][3] = sch[(r + 8) * 132 + kword + qc + 4];
                }
                #pragma unroll
                for (int ni = 0; ni < 2; ni++)
                    #pragma unroll
                    for (int mi = 0; mi < 2; mi++)
                        mma_f16(Co[mi][ni], Ap[mi], LVh[ki][ni][0], LVh[ki][ni][1]);
            }
            #pragma unroll
            for (int mi = 0; mi < 2; mi++)
                #pragma unroll
                for (int ni = 0; ni < 2; ni++) {
                    int v = mi * 16 + qr;
                    int d = ni * 8 + 2 * qc;
                    float2 p01, p23;
                    p01.x = Co[mi][ni][0]; p01.y = Co[mi][ni][1];
                    p23.x = Co[mi][ni][2]; p23.y = Co[mi][ni][3];
                    *(float2*)&pb[w * 520 + v * 16 + d] = p01;
                    *(float2*)&pb[w * 520 + (v + 8) * 16 + d] = p23;
                }
        }
        __syncthreads();

        {
            int v = tid >> 3;
            int d = (tid & 7) * 2;
            float2 s = make_float2(0.f, 0.f);
            #pragma unroll
            for (int ww = 0; ww < 8; ww++) {
                float2 p = *(float2*)&pb[ww * 520 + tid * 2];
                s.x += p.x; s.y += p.y;
            }
            float si = sinv[v];
            float2 r2 = *(const float2*)(g_r + ((size_t)((t * BB + b) * VV + v)) * FF + h * DHH + d);
            float2 res;
            res.x = r2.x * __expf(s.x * si);
            res.y = r2.y * __expf(s.y * si);
            *(float2*)(g_pre + ((size_t)(t * BB + b)) * (VV * FF)
                       + h * (VV * DHH) + v * DHH + d) = res;
        }
    }
}

// ---------------- launch ----------------
extern "C" void kernel_launch(void* const* d_in, const int* in_sizes, int n_in,
                              void* d_out, int out_size)
{
    const float* vehicles    = (const float*)d_in[0];
    const float* initial_pos = (const float*)d_in[1];
    const float* lanes       = (const float*)d_in[2];
    const unsigned char* mask_lanes = (const unsigned char*)d_in[3];
    const float* Wk = (const float*)d_in[4];
    const float* bk = (const float*)d_in[5];
    const float* Wv = (const float*)d_in[6];
    const float* bv = (const float*)d_in[7];
    const float* Wq = (const float*)d_in[8];
    const float* bq = (const float*)d_in[9];
    const float* Wr = (const float*)d_in[10];
    const float* br = (const float*)d_in[11];
    const float* Wc = (const float*)d_in[12];
    const float* bc = (const float*)d_in[13];
    float* out = (float*)d_out;

    cudaFuncSetAttribute(attn9_kernel,
                         cudaFuncAttributeMaxDynamicSharedMemorySize, BSMEM_BYTES);
    cudaFuncSetAttribute(attn9_kernel,
                         cudaFuncAttributePreferredSharedMemoryCarveout,
                         cudaSharedmemCarveoutMaxShared);

    float *gK, *gLV, *gq, *gr, *gpre;
    cudaGetSymbolAddress((void**)&gK,   g_Kproj);
    cudaGetSymbolAddress((void**)&gLV,  g_LV);
    cudaGetSymbolAddress((void**)&gq,   g_q);
    cudaGetSymbolAddress((void**)&gr,   g_r);
    cudaGetSymbolAddress((void**)&gpre, g_pre);

    // 1) lane projections + mask
    lane_proj_kernel<false><<<BB * LL / 32, 256>>>(lanes, Wk, bk, gK);
    lane_proj_kernel<true ><<<BB * LL / 32, 256>>>(lanes, Wv, bv, gLV);
    mask_kernel<<<1, 256>>>(mask_lanes);

    // 2) fused q, r projections (tensor cores)
    gemm_qr_tc<<<MROWS / 64, 256>>>(vehicles, initial_pos, Wq, bq, Wr, br, gq, gr);

    // 3) attention (tensor cores, f16x2 exp, fp16 PV)
    attn9_kernel<<<dim3(BB * HH, TT / ATB), 256, BSMEM_BYTES>>>();

    // 4) combine + residual (tensor cores)
    gemm_c_tc<<<MROWS / 64, 256>>>(gpre, Wc, bc, out, vehicles, initial_pos);
}